// round 1
// baseline (speedup 1.0000x reference)
#include <cuda_runtime.h>

#define NN 50000
#define EE 800000
#define D  128
#define G  8
#define C  10

// ---------------- scratch (static device globals; no allocs allowed) --------
__device__ float g_out_isqrt[NN];
__device__ float g_in_isqrt[NN];
__device__ float g_bufA[NN * D];
__device__ float g_bufB[NN * D];
__device__ float g_sums[G * D];
__device__ float g_counts[G];

// ---------------- utility: zero a float buffer ------------------------------
__global__ void k_zero(float* p, int n) {
    for (int i = blockIdx.x * blockDim.x + threadIdx.x; i < n;
         i += gridDim.x * blockDim.x)
        p[i] = 0.0f;
}

// ---------------- degrees ----------------------------------------------------
__global__ void k_degrees(const int* __restrict__ ei, int E,
                          float* __restrict__ outdeg, float* __restrict__ indeg) {
    int e = blockIdx.x * blockDim.x + threadIdx.x;
    if (e < E) {
        atomicAdd(&outdeg[ei[e]], 1.0f);
        atomicAdd(&indeg[ei[E + e]], 1.0f);
    }
}

__global__ void k_finalize_deg(float* a, float* b, int n) {
    int i = blockIdx.x * blockDim.x + threadIdx.x;
    if (i < n) {
        a[i] = rsqrtf(fmaxf(a[i], 1.0f));
        b[i] = rsqrtf(fmaxf(b[i], 1.0f));
    }
}

// ---------------- GEMM: Cm[r, :] = (A[r, :] * rs[r]) @ W  (K = N = 128) -----
// Classic 128x128 tile, BK=8, 256 threads, 8x8 per thread.
__global__ __launch_bounds__(256)
void k_gemm_rs(const float* __restrict__ A, const float* __restrict__ rs,
               const float* __restrict__ W, float* __restrict__ Cm, int nrows) {
    __shared__ float As[8 * 128];
    __shared__ float Ws[8 * 128];
    const int tid = threadIdx.x;
    const int rowBase = blockIdx.x * 128;
    const int tx = tid & 15;        // 0..15 -> cols tx*8
    const int ty = tid >> 4;        // 0..15 -> rows ty*8

    // A-tile load mapping: 128 rows x 8 k -> 256 float4 loads
    const int arow = tid >> 1;
    const int aq   = (tid & 1) * 4;
    const int grow = rowBase + arow;
    const bool arow_ok = (grow < nrows);
    const float scale = arow_ok ? rs[grow] : 0.0f;
    const float* Arow = A + (size_t)grow * D;

    // W-tile load mapping: 8 k x 128 cols -> 256 float4 loads
    const int wk = tid >> 5;
    const int wc = (tid & 31) * 4;

    float acc[8][8];
#pragma unroll
    for (int i = 0; i < 8; i++)
#pragma unroll
        for (int j = 0; j < 8; j++) acc[i][j] = 0.0f;

    for (int k0 = 0; k0 < D; k0 += 8) {
        float4 av = make_float4(0.f, 0.f, 0.f, 0.f);
        if (arow_ok) av = *(const float4*)(Arow + k0 + aq);
        As[(aq + 0) * 128 + arow] = av.x * scale;
        As[(aq + 1) * 128 + arow] = av.y * scale;
        As[(aq + 2) * 128 + arow] = av.z * scale;
        As[(aq + 3) * 128 + arow] = av.w * scale;
        *(float4*)(Ws + wk * 128 + wc) = *(const float4*)(W + (size_t)(k0 + wk) * D + wc);
        __syncthreads();

#pragma unroll
        for (int kk = 0; kk < 8; kk++) {
            float am[8], wn[8];
            *(float4*)(am)     = *(const float4*)(As + kk * 128 + ty * 8);
            *(float4*)(am + 4) = *(const float4*)(As + kk * 128 + ty * 8 + 4);
            *(float4*)(wn)     = *(const float4*)(Ws + kk * 128 + tx * 8);
            *(float4*)(wn + 4) = *(const float4*)(Ws + kk * 128 + tx * 8 + 4);
#pragma unroll
            for (int i = 0; i < 8; i++)
#pragma unroll
                for (int j = 0; j < 8; j++) acc[i][j] = fmaf(am[i], wn[j], acc[i][j]);
        }
        __syncthreads();
    }

#pragma unroll
    for (int i = 0; i < 8; i++) {
        int r = rowBase + ty * 8 + i;
        if (r < nrows) {
            float4 v0 = make_float4(acc[i][0], acc[i][1], acc[i][2], acc[i][3]);
            float4 v1 = make_float4(acc[i][4], acc[i][5], acc[i][6], acc[i][7]);
            *(float4*)(Cm + (size_t)r * D + tx * 8)     = v0;
            *(float4*)(Cm + (size_t)r * D + tx * 8 + 4) = v1;
        }
    }
}

// ---------------- SpMM scatter: B[dst] += A[src], one warp per edge ---------
__global__ void k_scatter(const int* __restrict__ ei, int E,
                          const float* __restrict__ A, float* __restrict__ B) {
    int t = blockIdx.x * blockDim.x + threadIdx.x;
    int e = t >> 5;
    if (e >= E) return;
    int lane = t & 31;
    int s = ei[e];
    int d = ei[E + e];
    float4 v = *(const float4*)(A + (size_t)s * D + lane * 4);
    float* dst = B + (size_t)d * D + lane * 4;
    asm volatile("red.global.add.v4.f32 [%0], {%1, %2, %3, %4};"
                 :: "l"(dst), "f"(v.x), "f"(v.y), "f"(v.z), "f"(v.w)
                 : "memory");
}

// ---------------- epilogue: out = relu(agg * in_isqrt[row] + b[col]) --------
__global__ void k_epilogue(const float* __restrict__ agg,
                           const float* __restrict__ isq,
                           const float* __restrict__ b,
                           float* __restrict__ out, int nrows) {
    int n4 = nrows * (D / 4);
    for (int i = blockIdx.x * blockDim.x + threadIdx.x; i < n4;
         i += gridDim.x * blockDim.x) {
        int row = i >> 5;              // D/4 = 32 float4 per row
        int c4 = (i & 31) * 4;
        float s = isq[row];
        float4 a = *(const float4*)(agg + (size_t)i * 4);
        float4 r;
        r.x = fmaxf(fmaf(a.x, s, b[c4 + 0]), 0.0f);
        r.y = fmaxf(fmaf(a.y, s, b[c4 + 1]), 0.0f);
        r.z = fmaxf(fmaf(a.z, s, b[c4 + 2]), 0.0f);
        r.w = fmaxf(fmaf(a.w, s, b[c4 + 3]), 0.0f);
        *(float4*)(out + (size_t)i * 4) = r;
    }
}

// ---------------- per-graph node counts -------------------------------------
__global__ void k_counts(const int* __restrict__ n2g, int n) {
    int i = blockIdx.x * blockDim.x + threadIdx.x;
    if (i < n) atomicAdd(&g_counts[n2g[i]], 1.0f);
}

// ---------------- pooling: per-graph feature sums ----------------------------
// 128 threads/block (one per dim), 256 nodes per block, smem [G][D] partials.
__global__ __launch_bounds__(128)
void k_pool(const float* __restrict__ h, const int* __restrict__ n2g, int n) {
    __shared__ float sacc[G * D];
    int tid = threadIdx.x;
#pragma unroll
    for (int g = 0; g < G; g++) sacc[g * D + tid] = 0.0f;
    __syncthreads();
    int base = blockIdx.x * 256;
    int end = min(base + 256, n);
    for (int node = base; node < end; node++) {
        int g = n2g[node];
        sacc[g * D + tid] += h[(size_t)node * D + tid];
    }
    __syncthreads();
#pragma unroll
    for (int g = 0; g < G; g++) {
        float v = sacc[g * D + tid];
        if (v != 0.0f) atomicAdd(&g_sums[g * D + tid], v);
    }
}

// ---------------- final: mean -> linear -> softmax ---------------------------
__global__ __launch_bounds__(128)
void k_final(const float* __restrict__ Wl, const float* __restrict__ bl,
             float* __restrict__ out) {
    __shared__ float hg[G * D];
    __shared__ float logits[G * C];
    int tid = threadIdx.x;
#pragma unroll
    for (int g = 0; g < G; g++)
        hg[g * D + tid] = g_sums[g * D + tid] / fmaxf(g_counts[g], 1.0f);
    __syncthreads();
    if (tid < G * C) {
        int g = tid / C, c = tid % C;
        float acc = bl[c];
        for (int k = 0; k < D; k++) acc = fmaf(hg[g * D + k], Wl[k * C + c], acc);
        logits[tid] = acc;
    }
    __syncthreads();
    if (tid < G) {
        float m = -1e30f;
        for (int c = 0; c < C; c++) m = fmaxf(m, logits[tid * C + c]);
        float s = 0.0f;
        float e[C];
        for (int c = 0; c < C; c++) { e[c] = expf(logits[tid * C + c] - m); s += e[c]; }
        float inv = 1.0f / s;
        for (int c = 0; c < C; c++) out[tid * C + c] = e[c] * inv;
    }
}

// ---------------- launch ------------------------------------------------------
extern "C" void kernel_launch(void* const* d_in, const int* in_sizes, int n_in,
                              void* d_out, int out_size) {
    const float* x   = (const float*)d_in[0];
    const int*   ei  = (const int*)d_in[1];
    const int*   n2g = (const int*)d_in[2];
    const float* W1  = (const float*)d_in[3];
    const float* b1  = (const float*)d_in[4];
    const float* W2  = (const float*)d_in[5];
    const float* b2  = (const float*)d_in[6];
    const float* Wl  = (const float*)d_in[7];
    const float* bl  = (const float*)d_in[8];
    float* out = (float*)d_out;

    const int N = in_sizes[2];          // 50000
    const int E = in_sizes[1] / 2;      // 800000

    float* outq = nullptr; cudaGetSymbolAddress((void**)&outq, g_out_isqrt);
    float* inq  = nullptr; cudaGetSymbolAddress((void**)&inq,  g_in_isqrt);
    float* bufA = nullptr; cudaGetSymbolAddress((void**)&bufA, g_bufA);
    float* bufB = nullptr; cudaGetSymbolAddress((void**)&bufB, g_bufB);
    float* sums = nullptr; cudaGetSymbolAddress((void**)&sums, g_sums);
    float* cnts = nullptr; cudaGetSymbolAddress((void**)&cnts, g_counts);

    const int ZB = 2048;
    // degrees
    k_zero<<<ZB, 256>>>(outq, N);
    k_zero<<<ZB, 256>>>(inq, N);
    k_degrees<<<(E + 255) / 256, 256>>>(ei, E, outq, inq);
    k_finalize_deg<<<(N + 255) / 256, 256>>>(outq, inq, N);

    const int gemmBlocks = (N + 127) / 128;
    const int scatBlocks = (int)(((long long)E * 32 + 255) / 256);

    // layer 1
    k_gemm_rs<<<gemmBlocks, 256>>>(x, outq, W1, bufA, N);
    k_zero<<<ZB, 256>>>(bufB, N * D);
    k_scatter<<<scatBlocks, 256>>>(ei, E, bufA, bufB);
    k_epilogue<<<ZB, 256>>>(bufB, inq, b1, bufA, N);

    // layer 2
    k_gemm_rs<<<gemmBlocks, 256>>>(bufA, outq, W2, bufB, N);
    k_zero<<<ZB, 256>>>(bufA, N * D);
    k_scatter<<<scatBlocks, 256>>>(ei, E, bufB, bufA);
    k_epilogue<<<ZB, 256>>>(bufA, inq, b2, bufB, N);

    // pooling + head
    k_zero<<<4, 256>>>(sums, G * D);
    k_zero<<<1, 32>>>(cnts, G);
    k_counts<<<(N + 255) / 256, 256>>>(n2g, N);
    k_pool<<<(N + 255) / 256, 128>>>(bufB, n2g, N);
    k_final<<<1, 128>>>(Wl, bl, out);
}

// round 2
// speedup vs baseline: 1.0573x; 1.0573x over previous
#include <cuda_runtime.h>

#define NN 50000
#define EE 800000
#define D  128
#define G  8
#define C  10

// ---------------- scratch (static device globals; no allocs allowed) --------
__device__ float g_out_isqrt[NN];
__device__ float g_in_isqrt[NN];
__device__ float g_bufA[NN * D];
__device__ float g_bufB[NN * D];
__device__ float g_sums[G * D];
__device__ float g_counts[G];
__device__ int   g_outcnt[NN];
__device__ int   g_incnt[NN];
__device__ int   g_rowptr[NN + 1];
__device__ int   g_cursor[NN];
__device__ int   g_csr[EE];

// ---------------- utility zeros ----------------------------------------------
__global__ void k_zero_i2(int* a, int* b, int n) {
    int i = blockIdx.x * blockDim.x + threadIdx.x;
    if (i < n) { a[i] = 0; b[i] = 0; }
}
__global__ void k_zero_f(float* p, int n) {
    int i = blockIdx.x * blockDim.x + threadIdx.x;
    if (i < n) p[i] = 0.0f;
}

// ---------------- degree histograms (int) ------------------------------------
__global__ void k_degcount(const int* __restrict__ ei, int E,
                           int* __restrict__ outc, int* __restrict__ inc) {
    int e = blockIdx.x * blockDim.x + threadIdx.x;
    if (e < E) {
        atomicAdd(&outc[ei[e]], 1);
        atomicAdd(&inc[ei[E + e]], 1);
    }
}

__global__ void k_out_isqrt(const int* __restrict__ outc, float* __restrict__ oq, int n) {
    int i = blockIdx.x * blockDim.x + threadIdx.x;
    if (i < n) oq[i] = rsqrtf((float)max(outc[i], 1));
}

// ---------------- single-block exclusive scan of in-degrees ------------------
// 1024 threads, each handles a contiguous chunk. Also emits in_isqrt + cursor.
__global__ __launch_bounds__(1024)
void k_scan(const int* __restrict__ inc, int n,
            int* __restrict__ rowp, int* __restrict__ cur,
            float* __restrict__ iq) {
    __shared__ int ssum[1024];
    int tid = threadIdx.x;
    int per = (n + 1023) / 1024;
    int start = tid * per;
    int end = min(start + per, n);
    int s = 0;
    for (int i = start; i < end; i++) s += inc[i];
    ssum[tid] = s;
    __syncthreads();
    for (int off = 1; off < 1024; off <<= 1) {
        int t = (tid >= off) ? ssum[tid - off] : 0;
        __syncthreads();
        ssum[tid] += t;
        __syncthreads();
    }
    int run = ssum[tid] - s;   // exclusive prefix
    for (int i = start; i < end; i++) {
        rowp[i] = run;
        cur[i] = run;
        int c = inc[i];
        iq[i] = rsqrtf((float)max(c, 1));
        run += c;
    }
    if (tid == 1023) rowp[n] = ssum[1023];
}

// ---------------- CSR fill: bucket src indices by dst -------------------------
__global__ void k_fill(const int* __restrict__ ei, int E,
                       int* __restrict__ cur, int* __restrict__ csr) {
    int e = blockIdx.x * blockDim.x + threadIdx.x;
    if (e < E) {
        int d = ei[E + e];
        int pos = atomicAdd(&cur[d], 1);
        csr[pos] = ei[e];
    }
}

// ---------------- GEMM: Cm[r, :] = (A[r, :] * rs[r]) @ W  (K = 128) ----------
// 128x128 tile, BK=8, 256 threads, 8x8 per thread, persistent over tiles.
__global__ __launch_bounds__(256)
void k_gemm_rs(const float* __restrict__ A, const float* __restrict__ rs,
               const float* __restrict__ W, float* __restrict__ Cm,
               int nrows, int ntiles) {
    __shared__ float As[8 * 128];
    __shared__ float Ws[8 * 128];
    const int tid = threadIdx.x;
    const int tx = tid & 15;
    const int ty = tid >> 4;
    const int arow = tid >> 1;
    const int aq   = (tid & 1) * 4;
    const int wk = tid >> 5;
    const int wc = (tid & 31) * 4;

    for (int tile = blockIdx.x; tile < ntiles; tile += gridDim.x) {
        const int rowBase = tile * 128;
        const int grow = rowBase + arow;
        const bool arow_ok = (grow < nrows);
        const float scale = arow_ok ? rs[grow] : 0.0f;
        const float* Arow = A + (size_t)grow * D;

        float acc[8][8];
#pragma unroll
        for (int i = 0; i < 8; i++)
#pragma unroll
            for (int j = 0; j < 8; j++) acc[i][j] = 0.0f;

        for (int k0 = 0; k0 < D; k0 += 8) {
            float4 av = make_float4(0.f, 0.f, 0.f, 0.f);
            if (arow_ok) av = *(const float4*)(Arow + k0 + aq);
            As[(aq + 0) * 128 + arow] = av.x * scale;
            As[(aq + 1) * 128 + arow] = av.y * scale;
            As[(aq + 2) * 128 + arow] = av.z * scale;
            As[(aq + 3) * 128 + arow] = av.w * scale;
            *(float4*)(Ws + wk * 128 + wc) =
                *(const float4*)(W + (size_t)(k0 + wk) * D + wc);
            __syncthreads();

#pragma unroll
            for (int kk = 0; kk < 8; kk++) {
                float am[8], wn[8];
                *(float4*)(am)     = *(const float4*)(As + kk * 128 + ty * 8);
                *(float4*)(am + 4) = *(const float4*)(As + kk * 128 + ty * 8 + 4);
                *(float4*)(wn)     = *(const float4*)(Ws + kk * 128 + tx * 8);
                *(float4*)(wn + 4) = *(const float4*)(Ws + kk * 128 + tx * 8 + 4);
#pragma unroll
                for (int i = 0; i < 8; i++)
#pragma unroll
                    for (int j = 0; j < 8; j++)
                        acc[i][j] = fmaf(am[i], wn[j], acc[i][j]);
            }
            __syncthreads();
        }

#pragma unroll
        for (int i = 0; i < 8; i++) {
            int r = rowBase + ty * 8 + i;
            if (r < nrows) {
                float4 v0 = make_float4(acc[i][0], acc[i][1], acc[i][2], acc[i][3]);
                float4 v1 = make_float4(acc[i][4], acc[i][5], acc[i][6], acc[i][7]);
                *(float4*)(Cm + (size_t)r * D + tx * 8)     = v0;
                *(float4*)(Cm + (size_t)r * D + tx * 8 + 4) = v1;
            }
        }
        __syncthreads();
    }
}

// ---------------- gather + fused epilogue -------------------------------------
// One warp per dst row: sum A[src] over in-edges, out = relu(sum*isq + b).
__global__ __launch_bounds__(256)
void k_gather(const int* __restrict__ csr, const int* __restrict__ rowp,
              const float* __restrict__ A, const float* __restrict__ isq,
              const float* __restrict__ b, float* __restrict__ out, int n) {
    int w = (blockIdx.x * blockDim.x + threadIdx.x) >> 5;
    if (w >= n) return;
    int lane = threadIdx.x & 31;
    int s0 = rowp[w], s1 = rowp[w + 1];
    float4 acc = make_float4(0.f, 0.f, 0.f, 0.f);
    const unsigned FULL = 0xffffffffu;
    int col = lane * 4;

    for (int base = s0; base < s1; base += 32) {
        int cnt = min(32, s1 - base);
        int myidx = (lane < cnt) ? csr[base + lane] : 0;
        int t = 0;
        for (; t + 4 <= cnt; t += 4) {
            int i0 = __shfl_sync(FULL, myidx, t + 0);
            int i1 = __shfl_sync(FULL, myidx, t + 1);
            int i2 = __shfl_sync(FULL, myidx, t + 2);
            int i3 = __shfl_sync(FULL, myidx, t + 3);
            float4 v0 = *(const float4*)(A + (size_t)i0 * D + col);
            float4 v1 = *(const float4*)(A + (size_t)i1 * D + col);
            float4 v2 = *(const float4*)(A + (size_t)i2 * D + col);
            float4 v3 = *(const float4*)(A + (size_t)i3 * D + col);
            acc.x += v0.x + v1.x + v2.x + v3.x;
            acc.y += v0.y + v1.y + v2.y + v3.y;
            acc.z += v0.z + v1.z + v2.z + v3.z;
            acc.w += v0.w + v1.w + v2.w + v3.w;
        }
        for (; t < cnt; t++) {
            int s = __shfl_sync(FULL, myidx, t);
            float4 v = *(const float4*)(A + (size_t)s * D + col);
            acc.x += v.x; acc.y += v.y; acc.z += v.z; acc.w += v.w;
        }
    }

    float sc = isq[w];
    float4 bb = *(const float4*)(b + col);
    float4 r;
    r.x = fmaxf(fmaf(acc.x, sc, bb.x), 0.0f);
    r.y = fmaxf(fmaf(acc.y, sc, bb.y), 0.0f);
    r.z = fmaxf(fmaf(acc.z, sc, bb.z), 0.0f);
    r.w = fmaxf(fmaf(acc.w, sc, bb.w), 0.0f);
    *(float4*)(out + (size_t)w * D + col) = r;
}

// ---------------- per-graph node counts ---------------------------------------
__global__ void k_counts(const int* __restrict__ n2g, int n) {
    int i = blockIdx.x * blockDim.x + threadIdx.x;
    if (i < n) atomicAdd(&g_counts[n2g[i]], 1.0f);
}

// ---------------- pooling: per-graph feature sums ------------------------------
__global__ __launch_bounds__(128)
void k_pool(const float* __restrict__ h, const int* __restrict__ n2g, int n) {
    __shared__ float sacc[G * D];
    int tid = threadIdx.x;
#pragma unroll
    for (int g = 0; g < G; g++) sacc[g * D + tid] = 0.0f;
    __syncthreads();
    int base = blockIdx.x * 256;
    int end = min(base + 256, n);
    for (int node = base; node < end; node++) {
        int g = n2g[node];
        sacc[g * D + tid] += h[(size_t)node * D + tid];
    }
    __syncthreads();
#pragma unroll
    for (int g = 0; g < G; g++) {
        float v = sacc[g * D + tid];
        if (v != 0.0f) atomicAdd(&g_sums[g * D + tid], v);
    }
}

// ---------------- final: mean -> linear -> softmax -----------------------------
__global__ __launch_bounds__(128)
void k_final(const float* __restrict__ Wl, const float* __restrict__ bl,
             float* __restrict__ out) {
    __shared__ float hg[G * D];
    __shared__ float logits[G * C];
    int tid = threadIdx.x;
#pragma unroll
    for (int g = 0; g < G; g++)
        hg[g * D + tid] = g_sums[g * D + tid] / fmaxf(g_counts[g], 1.0f);
    __syncthreads();
    if (tid < G * C) {
        int g = tid / C, c = tid % C;
        float acc = bl[c];
        for (int k = 0; k < D; k++) acc = fmaf(hg[g * D + k], Wl[k * C + c], acc);
        logits[tid] = acc;
    }
    __syncthreads();
    if (tid < G) {
        float m = -1e30f;
        for (int c = 0; c < C; c++) m = fmaxf(m, logits[tid * C + c]);
        float s = 0.0f;
        float e[C];
        for (int c = 0; c < C; c++) { e[c] = expf(logits[tid * C + c] - m); s += e[c]; }
        float inv = 1.0f / s;
        for (int c = 0; c < C; c++) out[tid * C + c] = e[c] * inv;
    }
}

// ---------------- launch --------------------------------------------------------
extern "C" void kernel_launch(void* const* d_in, const int* in_sizes, int n_in,
                              void* d_out, int out_size) {
    const float* x   = (const float*)d_in[0];
    const int*   ei  = (const int*)d_in[1];
    const int*   n2g = (const int*)d_in[2];
    const float* W1  = (const float*)d_in[3];
    const float* b1  = (const float*)d_in[4];
    const float* W2  = (const float*)d_in[5];
    const float* b2  = (const float*)d_in[6];
    const float* Wl  = (const float*)d_in[7];
    const float* bl  = (const float*)d_in[8];
    float* out = (float*)d_out;

    const int N = in_sizes[2];          // 50000
    const int E = in_sizes[1] / 2;      // 800000

    float* outq = nullptr; cudaGetSymbolAddress((void**)&outq, g_out_isqrt);
    float* inq  = nullptr; cudaGetSymbolAddress((void**)&inq,  g_in_isqrt);
    float* bufA = nullptr; cudaGetSymbolAddress((void**)&bufA, g_bufA);
    float* bufB = nullptr; cudaGetSymbolAddress((void**)&bufB, g_bufB);
    float* sums = nullptr; cudaGetSymbolAddress((void**)&sums, g_sums);
    float* cnts = nullptr; cudaGetSymbolAddress((void**)&cnts, g_counts);
    int* outc = nullptr; cudaGetSymbolAddress((void**)&outc, g_outcnt);
    int* inc  = nullptr; cudaGetSymbolAddress((void**)&inc,  g_incnt);
    int* rowp = nullptr; cudaGetSymbolAddress((void**)&rowp, g_rowptr);
    int* cur  = nullptr; cudaGetSymbolAddress((void**)&cur,  g_cursor);
    int* csr  = nullptr; cudaGetSymbolAddress((void**)&csr,  g_csr);

    // ---- CSR build + degree norms (once) ----
    k_zero_i2<<<(N + 255) / 256, 256>>>(outc, inc, N);
    k_degcount<<<(E + 255) / 256, 256>>>(ei, E, outc, inc);
    k_out_isqrt<<<(N + 255) / 256, 256>>>(outc, outq, N);
    k_scan<<<1, 1024>>>(inc, N, rowp, cur, inq);
    k_fill<<<(E + 255) / 256, 256>>>(ei, E, cur, csr);

    const int ntiles = (N + 127) / 128;
    const int gemmBlocks = 296;                       // 2 * 148 SMs, persistent
    const int gatherBlocks = (N * 32 + 255) / 256;    // 1 warp per row

    // layer 1: h1 = relu( gather((x*oq)@W1) * iq + b1 )
    k_gemm_rs<<<gemmBlocks, 256>>>(x, outq, W1, bufA, N, ntiles);
    k_gather<<<gatherBlocks, 256>>>(csr, rowp, bufA, inq, b1, bufB, N);

    // layer 2
    k_gemm_rs<<<gemmBlocks, 256>>>(bufB, outq, W2, bufA, N, ntiles);
    k_gather<<<gatherBlocks, 256>>>(csr, rowp, bufA, inq, b2, bufB, N);

    // pooling + head
    k_zero_f<<<4, 256>>>(sums, G * D);
    k_zero_f<<<1, 32>>>(cnts, G);
    k_counts<<<(N + 255) / 256, 256>>>(n2g, N);
    k_pool<<<(N + 255) / 256, 128>>>(bufB, n2g, N);
    k_final<<<1, 128>>>(Wl, bl, out);
}

// round 3
// speedup vs baseline: 1.3698x; 1.2956x over previous
#include <cuda_runtime.h>

#define NN 50000
#define EE 800000
#define D  128
#define G  8
#define C  10

// ---------------- scratch (static device globals; no allocs allowed) --------
__device__ float g_out_isqrt[NN];
__device__ float g_in_isqrt[NN];
__device__ float g_bufA[NN * D];
__device__ float g_bufB[NN * D];
__device__ float g_sums[G * D];
__device__ float g_counts[G];
__device__ int   g_outcnt[NN];
__device__ int   g_incnt[NN];
__device__ int   g_rowptr[NN + 1];
__device__ int   g_cursor[NN];
__device__ int   g_csr[EE];
__device__ int   g_bsums[256];

// ---------------- utility zeros ----------------------------------------------
__global__ void k_zero_i2(int* a, int* b, int n) {
    int i = blockIdx.x * blockDim.x + threadIdx.x;
    if (i < n) { a[i] = 0; b[i] = 0; }
}
__global__ void k_zero_f(float* p, int n) {
    int i = blockIdx.x * blockDim.x + threadIdx.x;
    if (i < n) p[i] = 0.0f;
}

// ---------------- degree histograms (int) ------------------------------------
__global__ void k_degcount(const int* __restrict__ ei, int E,
                           int* __restrict__ outc, int* __restrict__ inc) {
    int e = blockIdx.x * blockDim.x + threadIdx.x;
    if (e < E) {
        atomicAdd(&outc[ei[e]], 1);
        atomicAdd(&inc[ei[E + e]], 1);
    }
}

// ---------------- parallel coalesced scan (3 passes) --------------------------
__device__ __forceinline__ int warp_incl_scan(int v, int lane) {
#pragma unroll
    for (int o = 1; o < 32; o <<= 1) {
        int t = __shfl_up_sync(0xffffffffu, v, o);
        if (lane >= o) v += t;
    }
    return v;
}

// block-wide inclusive scan for 256 threads; returns inclusive, total via smem
__device__ __forceinline__ int block_incl_scan(int v, int tid, int* ws) {
    int lane = tid & 31, wid = tid >> 5;
    int s = warp_incl_scan(v, lane);
    if (lane == 31) ws[wid] = s;
    __syncthreads();
    if (wid == 0) {
        int t = (lane < 8) ? ws[lane] : 0;
        t = warp_incl_scan(t, lane);
        if (lane < 8) ws[lane] = t;
    }
    __syncthreads();
    return s + (wid > 0 ? ws[wid - 1] : 0);
}

// pass 1: per-block (256-wide) sums
__global__ __launch_bounds__(256)
void k_scan1(const int* __restrict__ inc, int n, int* __restrict__ bsums) {
    __shared__ int ws[8];
    int tid = threadIdx.x;
    int i = blockIdx.x * 256 + tid;
    int v = (i < n) ? inc[i] : 0;
    int incl = block_incl_scan(v, tid, ws);
    if (tid == 255) bsums[blockIdx.x] = incl;
}

// pass 2: exclusive scan of <=256 block sums in one block; set rowp[n]=E
__global__ __launch_bounds__(256)
void k_scan2(int* __restrict__ bsums, int nb, int E, int* __restrict__ rowp, int n) {
    __shared__ int ws[8];
    int tid = threadIdx.x;
    int v = (tid < nb) ? bsums[tid] : 0;
    int incl = block_incl_scan(v, tid, ws);
    if (tid < nb) bsums[tid] = incl - v;
    if (tid == 0) rowp[n] = E;
}

// pass 3: rescan each tile + block offset; emit rowp, cursor, in_isqrt, out_isqrt
__global__ __launch_bounds__(256)
void k_scan3(const int* __restrict__ inc, const int* __restrict__ outc, int n,
             const int* __restrict__ bsums, int* __restrict__ rowp,
             int* __restrict__ cur, float* __restrict__ iq, float* __restrict__ oq) {
    __shared__ int ws[8];
    int tid = threadIdx.x;
    int i = blockIdx.x * 256 + tid;
    int v = (i < n) ? inc[i] : 0;
    int incl = block_incl_scan(v, tid, ws);
    if (i < n) {
        int ex = incl - v + bsums[blockIdx.x];
        rowp[i] = ex;
        cur[i] = ex;
        iq[i] = rsqrtf((float)max(v, 1));
        oq[i] = rsqrtf((float)max(outc[i], 1));
    }
}

// ---------------- CSR fill: bucket src indices by dst -------------------------
__global__ void k_fill(const int* __restrict__ ei, int E,
                       int* __restrict__ cur, int* __restrict__ csr) {
    int e = blockIdx.x * blockDim.x + threadIdx.x;
    if (e < E) {
        int d = ei[E + e];
        int pos = atomicAdd(&cur[d], 1);
        csr[pos] = ei[e];
    }
}

// ---------------- GEMM: Cm[r, :] = (A[r, :] * rs[r]) @ W  (K = 128) ----------
// 128x128 tile, BK=8, 256 threads, 8x8 per thread, persistent over tiles.
__global__ __launch_bounds__(256)
void k_gemm_rs(const float* __restrict__ A, const float* __restrict__ rs,
               const float* __restrict__ W, float* __restrict__ Cm,
               int nrows, int ntiles) {
    __shared__ float As[8 * 128];
    __shared__ float Ws[8 * 128];
    const int tid = threadIdx.x;
    const int tx = tid & 15;
    const int ty = tid >> 4;
    const int arow = tid >> 1;
    const int aq   = (tid & 1) * 4;
    const int wk = tid >> 5;
    const int wc = (tid & 31) * 4;

    for (int tile = blockIdx.x; tile < ntiles; tile += gridDim.x) {
        const int rowBase = tile * 128;
        const int grow = rowBase + arow;
        const bool arow_ok = (grow < nrows);
        const float scale = arow_ok ? rs[grow] : 0.0f;
        const float* Arow = A + (size_t)grow * D;

        float acc[8][8];
#pragma unroll
        for (int i = 0; i < 8; i++)
#pragma unroll
            for (int j = 0; j < 8; j++) acc[i][j] = 0.0f;

        for (int k0 = 0; k0 < D; k0 += 8) {
            float4 av = make_float4(0.f, 0.f, 0.f, 0.f);
            if (arow_ok) av = *(const float4*)(Arow + k0 + aq);
            As[(aq + 0) * 128 + arow] = av.x * scale;
            As[(aq + 1) * 128 + arow] = av.y * scale;
            As[(aq + 2) * 128 + arow] = av.z * scale;
            As[(aq + 3) * 128 + arow] = av.w * scale;
            *(float4*)(Ws + wk * 128 + wc) =
                *(const float4*)(W + (size_t)(k0 + wk) * D + wc);
            __syncthreads();

#pragma unroll
            for (int kk = 0; kk < 8; kk++) {
                float am[8], wn[8];
                *(float4*)(am)     = *(const float4*)(As + kk * 128 + ty * 8);
                *(float4*)(am + 4) = *(const float4*)(As + kk * 128 + ty * 8 + 4);
                *(float4*)(wn)     = *(const float4*)(Ws + kk * 128 + tx * 8);
                *(float4*)(wn + 4) = *(const float4*)(Ws + kk * 128 + tx * 8 + 4);
#pragma unroll
                for (int i = 0; i < 8; i++)
#pragma unroll
                    for (int j = 0; j < 8; j++)
                        acc[i][j] = fmaf(am[i], wn[j], acc[i][j]);
            }
            __syncthreads();
        }

#pragma unroll
        for (int i = 0; i < 8; i++) {
            int r = rowBase + ty * 8 + i;
            if (r < nrows) {
                float4 v0 = make_float4(acc[i][0], acc[i][1], acc[i][2], acc[i][3]);
                float4 v1 = make_float4(acc[i][4], acc[i][5], acc[i][6], acc[i][7]);
                *(float4*)(Cm + (size_t)r * D + tx * 8)     = v0;
                *(float4*)(Cm + (size_t)r * D + tx * 8 + 4) = v1;
            }
        }
        __syncthreads();
    }
}

// ---------------- gather + fused epilogue -------------------------------------
// One warp per dst row: sum A[src] over in-edges, out = relu(sum*isq + b).
__global__ __launch_bounds__(256)
void k_gather(const int* __restrict__ csr, const int* __restrict__ rowp,
              const float* __restrict__ A, const float* __restrict__ isq,
              const float* __restrict__ b, float* __restrict__ out, int n) {
    int w = (blockIdx.x * blockDim.x + threadIdx.x) >> 5;
    if (w >= n) return;
    int lane = threadIdx.x & 31;
    int s0 = rowp[w], s1 = rowp[w + 1];
    float4 acc = make_float4(0.f, 0.f, 0.f, 0.f);
    const unsigned FULL = 0xffffffffu;
    int col = lane * 4;

    for (int base = s0; base < s1; base += 32) {
        int cnt = min(32, s1 - base);
        int myidx = (lane < cnt) ? csr[base + lane] : 0;
        int t = 0;
        for (; t + 4 <= cnt; t += 4) {
            int i0 = __shfl_sync(FULL, myidx, t + 0);
            int i1 = __shfl_sync(FULL, myidx, t + 1);
            int i2 = __shfl_sync(FULL, myidx, t + 2);
            int i3 = __shfl_sync(FULL, myidx, t + 3);
            float4 v0 = *(const float4*)(A + (size_t)i0 * D + col);
            float4 v1 = *(const float4*)(A + (size_t)i1 * D + col);
            float4 v2 = *(const float4*)(A + (size_t)i2 * D + col);
            float4 v3 = *(const float4*)(A + (size_t)i3 * D + col);
            acc.x += v0.x + v1.x + v2.x + v3.x;
            acc.y += v0.y + v1.y + v2.y + v3.y;
            acc.z += v0.z + v1.z + v2.z + v3.z;
            acc.w += v0.w + v1.w + v2.w + v3.w;
        }
        for (; t < cnt; t++) {
            int s = __shfl_sync(FULL, myidx, t);
            float4 v = *(const float4*)(A + (size_t)s * D + col);
            acc.x += v.x; acc.y += v.y; acc.z += v.z; acc.w += v.w;
        }
    }

    float sc = isq[w];
    float4 bb = *(const float4*)(b + col);
    float4 r;
    r.x = fmaxf(fmaf(acc.x, sc, bb.x), 0.0f);
    r.y = fmaxf(fmaf(acc.y, sc, bb.y), 0.0f);
    r.z = fmaxf(fmaf(acc.z, sc, bb.z), 0.0f);
    r.w = fmaxf(fmaf(acc.w, sc, bb.w), 0.0f);
    *(float4*)(out + (size_t)w * D + col) = r;
}

// ---------------- per-graph node counts ---------------------------------------
__global__ void k_counts(const int* __restrict__ n2g, int n) {
    int i = blockIdx.x * blockDim.x + threadIdx.x;
    if (i < n) atomicAdd(&g_counts[n2g[i]], 1.0f);
}

// ---------------- pooling: per-graph feature sums ------------------------------
__global__ __launch_bounds__(128)
void k_pool(const float* __restrict__ h, const int* __restrict__ n2g, int n) {
    __shared__ float sacc[G * D];
    int tid = threadIdx.x;
#pragma unroll
    for (int g = 0; g < G; g++) sacc[g * D + tid] = 0.0f;
    __syncthreads();
    int base = blockIdx.x * 256;
    int end = min(base + 256, n);
    for (int node = base; node < end; node++) {
        int g = n2g[node];
        sacc[g * D + tid] += h[(size_t)node * D + tid];
    }
    __syncthreads();
#pragma unroll
    for (int g = 0; g < G; g++) {
        float v = sacc[g * D + tid];
        if (v != 0.0f) atomicAdd(&g_sums[g * D + tid], v);
    }
}

// ---------------- final: mean -> linear -> softmax -----------------------------
__global__ __launch_bounds__(128)
void k_final(const float* __restrict__ Wl, const float* __restrict__ bl,
             float* __restrict__ out) {
    __shared__ float hg[G * D];
    __shared__ float logits[G * C];
    int tid = threadIdx.x;
#pragma unroll
    for (int g = 0; g < G; g++)
        hg[g * D + tid] = g_sums[g * D + tid] / fmaxf(g_counts[g], 1.0f);
    __syncthreads();
    if (tid < G * C) {
        int g = tid / C, c = tid % C;
        float acc = bl[c];
        for (int k = 0; k < D; k++) acc = fmaf(hg[g * D + k], Wl[k * C + c], acc);
        logits[tid] = acc;
    }
    __syncthreads();
    if (tid < G) {
        float m = -1e30f;
        for (int c = 0; c < C; c++) m = fmaxf(m, logits[tid * C + c]);
        float s = 0.0f;
        float e[C];
        for (int c = 0; c < C; c++) { e[c] = expf(logits[tid * C + c] - m); s += e[c]; }
        float inv = 1.0f / s;
        for (int c = 0; c < C; c++) out[tid * C + c] = e[c] * inv;
    }
}

// ---------------- launch --------------------------------------------------------
extern "C" void kernel_launch(void* const* d_in, const int* in_sizes, int n_in,
                              void* d_out, int out_size) {
    const float* x   = (const float*)d_in[0];
    const int*   ei  = (const int*)d_in[1];
    const int*   n2g = (const int*)d_in[2];
    const float* W1  = (const float*)d_in[3];
    const float* b1  = (const float*)d_in[4];
    const float* W2  = (const float*)d_in[5];
    const float* b2  = (const float*)d_in[6];
    const float* Wl  = (const float*)d_in[7];
    const float* bl  = (const float*)d_in[8];
    float* out = (float*)d_out;

    const int N = in_sizes[2];          // 50000
    const int E = in_sizes[1] / 2;      // 800000

    float* outq = nullptr; cudaGetSymbolAddress((void**)&outq, g_out_isqrt);
    float* inq  = nullptr; cudaGetSymbolAddress((void**)&inq,  g_in_isqrt);
    float* bufA = nullptr; cudaGetSymbolAddress((void**)&bufA, g_bufA);
    float* bufB = nullptr; cudaGetSymbolAddress((void**)&bufB, g_bufB);
    float* sums = nullptr; cudaGetSymbolAddress((void**)&sums, g_sums);
    float* cnts = nullptr; cudaGetSymbolAddress((void**)&cnts, g_counts);
    int* outc = nullptr; cudaGetSymbolAddress((void**)&outc, g_outcnt);
    int* inc  = nullptr; cudaGetSymbolAddress((void**)&inc,  g_incnt);
    int* rowp = nullptr; cudaGetSymbolAddress((void**)&rowp, g_rowptr);
    int* cur  = nullptr; cudaGetSymbolAddress((void**)&cur,  g_cursor);
    int* csr  = nullptr; cudaGetSymbolAddress((void**)&csr,  g_csr);
    int* bsum = nullptr; cudaGetSymbolAddress((void**)&bsum, g_bsums);

    const int nb = (N + 255) / 256;     // 196 <= 256

    // ---- CSR build + degree norms (once) ----
    k_zero_i2<<<nb, 256>>>(outc, inc, N);
    k_degcount<<<(E + 255) / 256, 256>>>(ei, E, outc, inc);
    k_scan1<<<nb, 256>>>(inc, N, bsum);
    k_scan2<<<1, 256>>>(bsum, nb, E, rowp, N);
    k_scan3<<<nb, 256>>>(inc, outc, N, bsum, rowp, cur, inq, outq);
    k_fill<<<(E + 255) / 256, 256>>>(ei, E, cur, csr);

    const int ntiles = (N + 127) / 128;
    const int gemmBlocks = 296;                       // 2 * 148 SMs, persistent
    const int gatherBlocks = (N * 32 + 255) / 256;    // 1 warp per row

    // layer 1: h1 = relu( gather((x*oq)@W1) * iq + b1 )
    k_gemm_rs<<<gemmBlocks, 256>>>(x, outq, W1, bufA, N, ntiles);
    k_gather<<<gatherBlocks, 256>>>(csr, rowp, bufA, inq, b1, bufB, N);

    // layer 2
    k_gemm_rs<<<gemmBlocks, 256>>>(bufB, outq, W2, bufA, N, ntiles);
    k_gather<<<gatherBlocks, 256>>>(csr, rowp, bufA, inq, b2, bufB, N);

    // pooling + head
    k_zero_f<<<4, 256>>>(sums, G * D);
    k_zero_f<<<1, 32>>>(cnts, G);
    k_counts<<<nb, 256>>>(n2g, N);
    k_pool<<<nb, 128>>>(bufB, n2g, N);
    k_final<<<1, 128>>>(Wl, bl, out);
}

// round 4
// speedup vs baseline: 1.3818x; 1.0087x over previous
#include <cuda_runtime.h>

#define NN 50000
#define EE 800000
#define D  128
#define G  8
#define C  10

// ---------------- scratch (static device globals; no allocs allowed) --------
__device__ float g_out_isqrt[NN];
__device__ float g_in_isqrt[NN];
__device__ float g_bufA[NN * D];
__device__ float g_bufB[NN * D];
__device__ float g_sums[G * D];
__device__ float g_counts[G];
__device__ int   g_outcnt[NN];
__device__ int   g_incnt[NN];
__device__ int   g_rowptr[NN + 1];
__device__ int   g_cursor[NN];
__device__ int   g_csr[EE];
__device__ int   g_bsums[256];

// ---------------- utility zeros ----------------------------------------------
__global__ void k_zero_i2(int* a, int* b, int n) {
    int i = blockIdx.x * blockDim.x + threadIdx.x;
    if (i < n) { a[i] = 0; b[i] = 0; }
}
__global__ void k_zero_f(float* p, int n) {
    int i = blockIdx.x * blockDim.x + threadIdx.x;
    if (i < n) p[i] = 0.0f;
}

// ---------------- degree histograms (int) ------------------------------------
__global__ void k_degcount(const int* __restrict__ ei, int E,
                           int* __restrict__ outc, int* __restrict__ inc) {
    int e = blockIdx.x * blockDim.x + threadIdx.x;
    if (e < E) {
        atomicAdd(&outc[ei[e]], 1);
        atomicAdd(&inc[ei[E + e]], 1);
    }
}

// ---------------- parallel coalesced scan (3 passes) --------------------------
__device__ __forceinline__ int warp_incl_scan(int v, int lane) {
#pragma unroll
    for (int o = 1; o < 32; o <<= 1) {
        int t = __shfl_up_sync(0xffffffffu, v, o);
        if (lane >= o) v += t;
    }
    return v;
}

__device__ __forceinline__ int block_incl_scan(int v, int tid, int* ws) {
    int lane = tid & 31, wid = tid >> 5;
    int s = warp_incl_scan(v, lane);
    if (lane == 31) ws[wid] = s;
    __syncthreads();
    if (wid == 0) {
        int t = (lane < 8) ? ws[lane] : 0;
        t = warp_incl_scan(t, lane);
        if (lane < 8) ws[lane] = t;
    }
    __syncthreads();
    return s + (wid > 0 ? ws[wid - 1] : 0);
}

__global__ __launch_bounds__(256)
void k_scan1(const int* __restrict__ inc, int n, int* __restrict__ bsums) {
    __shared__ int ws[8];
    int tid = threadIdx.x;
    int i = blockIdx.x * 256 + tid;
    int v = (i < n) ? inc[i] : 0;
    int incl = block_incl_scan(v, tid, ws);
    if (tid == 255) bsums[blockIdx.x] = incl;
}

__global__ __launch_bounds__(256)
void k_scan2(int* __restrict__ bsums, int nb, int E, int* __restrict__ rowp, int n) {
    __shared__ int ws[8];
    int tid = threadIdx.x;
    int v = (tid < nb) ? bsums[tid] : 0;
    int incl = block_incl_scan(v, tid, ws);
    if (tid < nb) bsums[tid] = incl - v;
    if (tid == 0) rowp[n] = E;
}

__global__ __launch_bounds__(256)
void k_scan3(const int* __restrict__ inc, const int* __restrict__ outc, int n,
             const int* __restrict__ bsums, int* __restrict__ rowp,
             int* __restrict__ cur, float* __restrict__ iq, float* __restrict__ oq) {
    __shared__ int ws[8];
    int tid = threadIdx.x;
    int i = blockIdx.x * 256 + tid;
    int v = (i < n) ? inc[i] : 0;
    int incl = block_incl_scan(v, tid, ws);
    if (i < n) {
        int ex = incl - v + bsums[blockIdx.x];
        rowp[i] = ex;
        cur[i] = ex;
        iq[i] = rsqrtf((float)max(v, 1));
        oq[i] = rsqrtf((float)max(outc[i], 1));
    }
}

// ---------------- CSR fill: bucket src indices by dst -------------------------
__global__ void k_fill(const int* __restrict__ ei, int E,
                       int* __restrict__ cur, int* __restrict__ csr) {
    int e = blockIdx.x * blockDim.x + threadIdx.x;
    if (e < E) {
        int d = ei[E + e];
        int pos = atomicAdd(&cur[d], 1);
        csr[pos] = ei[e];
    }
}

// ---------------- packed f32x2 helpers -----------------------------------------
__device__ __forceinline__ unsigned long long pack_dup(float a) {
    unsigned long long r;
    unsigned u = __float_as_uint(a);
    asm("mov.b64 %0, {%1, %1};" : "=l"(r) : "r"(u));
    return r;
}
__device__ __forceinline__ void fma_x2(unsigned long long& acc,
                                       unsigned long long a,
                                       unsigned long long b) {
    asm("fma.rn.f32x2 %0, %1, %2, %0;" : "+l"(acc) : "l"(a), "l"(b));
}
__device__ __forceinline__ float2 unpack_x2(unsigned long long v) {
    unsigned lo, hi;
    asm("mov.b64 {%0, %1}, %2;" : "=r"(lo), "=r"(hi) : "l"(v));
    return make_float2(__uint_as_float(lo), __uint_as_float(hi));
}

// ---------------- GEMM: Cm[r, :] = (A[r, :] * rs[r]) @ W  (K = 128) ----------
// 128x128 tile, BK=8, 256 threads, 8x8 per thread via packed f32x2 FMAs.
__global__ __launch_bounds__(256)
void k_gemm_rs(const float* __restrict__ A, const float* __restrict__ rs,
               const float* __restrict__ W, float* __restrict__ Cm,
               int nrows, int ntiles) {
    __shared__ float As[8 * 128];
    __shared__ float Ws[8 * 128];
    const int tid = threadIdx.x;
    const int tx = tid & 15;
    const int ty = tid >> 4;
    const int arow = tid >> 1;
    const int aq   = (tid & 1) * 4;
    const int wk = tid >> 5;
    const int wc = (tid & 31) * 4;

    for (int tile = blockIdx.x; tile < ntiles; tile += gridDim.x) {
        const int rowBase = tile * 128;
        const int grow = rowBase + arow;
        const bool arow_ok = (grow < nrows);
        const float scale = arow_ok ? rs[grow] : 0.0f;
        const float* Arow = A + (size_t)grow * D;

        unsigned long long acc2[8][4];
#pragma unroll
        for (int i = 0; i < 8; i++)
#pragma unroll
            for (int j = 0; j < 4; j++) acc2[i][j] = 0ull;

        for (int k0 = 0; k0 < D; k0 += 8) {
            float4 av = make_float4(0.f, 0.f, 0.f, 0.f);
            if (arow_ok) av = *(const float4*)(Arow + k0 + aq);
            As[(aq + 0) * 128 + arow] = av.x * scale;
            As[(aq + 1) * 128 + arow] = av.y * scale;
            As[(aq + 2) * 128 + arow] = av.z * scale;
            As[(aq + 3) * 128 + arow] = av.w * scale;
            *(float4*)(Ws + wk * 128 + wc) =
                *(const float4*)(W + (size_t)(k0 + wk) * D + wc);
            __syncthreads();

#pragma unroll
            for (int kk = 0; kk < 8; kk++) {
                float am[8];
                *(float4*)(am)     = *(const float4*)(As + kk * 128 + ty * 8);
                *(float4*)(am + 4) = *(const float4*)(As + kk * 128 + ty * 8 + 4);
                // wn pairs loaded directly as 64-bit lanes (2 x LDS.128)
                ulonglong2 w01 = *(const ulonglong2*)(Ws + kk * 128 + tx * 8);
                ulonglong2 w23 = *(const ulonglong2*)(Ws + kk * 128 + tx * 8 + 4);
                unsigned long long wn2[4] = {w01.x, w01.y, w23.x, w23.y};
#pragma unroll
                for (int i = 0; i < 8; i++) {
                    unsigned long long a2 = pack_dup(am[i]);
#pragma unroll
                    for (int j = 0; j < 4; j++) fma_x2(acc2[i][j], a2, wn2[j]);
                }
            }
            __syncthreads();
        }

#pragma unroll
        for (int i = 0; i < 8; i++) {
            int r = rowBase + ty * 8 + i;
            if (r < nrows) {
                float2 p0 = unpack_x2(acc2[i][0]);
                float2 p1 = unpack_x2(acc2[i][1]);
                float2 p2 = unpack_x2(acc2[i][2]);
                float2 p3 = unpack_x2(acc2[i][3]);
                float4 v0 = make_float4(p0.x, p0.y, p1.x, p1.y);
                float4 v1 = make_float4(p2.x, p2.y, p3.x, p3.y);
                *(float4*)(Cm + (size_t)r * D + tx * 8)     = v0;
                *(float4*)(Cm + (size_t)r * D + tx * 8 + 4) = v1;
            }
        }
        __syncthreads();
    }
}

// ---------------- gather + fused epilogue -------------------------------------
__global__ __launch_bounds__(256)
void k_gather(const int* __restrict__ csr, const int* __restrict__ rowp,
              const float* __restrict__ A, const float* __restrict__ isq,
              const float* __restrict__ b, float* __restrict__ out, int n) {
    int w = (blockIdx.x * blockDim.x + threadIdx.x) >> 5;
    if (w >= n) return;
    int lane = threadIdx.x & 31;
    int s0 = rowp[w], s1 = rowp[w + 1];
    float4 acc = make_float4(0.f, 0.f, 0.f, 0.f);
    const unsigned FULL = 0xffffffffu;
    int col = lane * 4;

    for (int base = s0; base < s1; base += 32) {
        int cnt = min(32, s1 - base);
        int myidx = (lane < cnt) ? csr[base + lane] : 0;
        int t = 0;
        for (; t + 4 <= cnt; t += 4) {
            int i0 = __shfl_sync(FULL, myidx, t + 0);
            int i1 = __shfl_sync(FULL, myidx, t + 1);
            int i2 = __shfl_sync(FULL, myidx, t + 2);
            int i3 = __shfl_sync(FULL, myidx, t + 3);
            float4 v0 = *(const float4*)(A + (size_t)i0 * D + col);
            float4 v1 = *(const float4*)(A + (size_t)i1 * D + col);
            float4 v2 = *(const float4*)(A + (size_t)i2 * D + col);
            float4 v3 = *(const float4*)(A + (size_t)i3 * D + col);
            acc.x += v0.x + v1.x + v2.x + v3.x;
            acc.y += v0.y + v1.y + v2.y + v3.y;
            acc.z += v0.z + v1.z + v2.z + v3.z;
            acc.w += v0.w + v1.w + v2.w + v3.w;
        }
        for (; t < cnt; t++) {
            int s = __shfl_sync(FULL, myidx, t);
            float4 v = *(const float4*)(A + (size_t)s * D + col);
            acc.x += v.x; acc.y += v.y; acc.z += v.z; acc.w += v.w;
        }
    }

    float sc = isq[w];
    float4 bb = *(const float4*)(b + col);
    float4 r;
    r.x = fmaxf(fmaf(acc.x, sc, bb.x), 0.0f);
    r.y = fmaxf(fmaf(acc.y, sc, bb.y), 0.0f);
    r.z = fmaxf(fmaf(acc.z, sc, bb.z), 0.0f);
    r.w = fmaxf(fmaf(acc.w, sc, bb.w), 0.0f);
    *(float4*)(out + (size_t)w * D + col) = r;
}

// ---------------- per-graph node counts ---------------------------------------
__global__ void k_counts(const int* __restrict__ n2g, int n) {
    int i = blockIdx.x * blockDim.x + threadIdx.x;
    if (i < n) atomicAdd(&g_counts[n2g[i]], 1.0f);
}

// ---------------- pooling: per-graph feature sums ------------------------------
__global__ __launch_bounds__(128)
void k_pool(const float* __restrict__ h, const int* __restrict__ n2g, int n) {
    __shared__ float sacc[G * D];
    int tid = threadIdx.x;
#pragma unroll
    for (int g = 0; g < G; g++) sacc[g * D + tid] = 0.0f;
    __syncthreads();
    int base = blockIdx.x * 256;
    int end = min(base + 256, n);
    for (int node = base; node < end; node++) {
        int g = n2g[node];
        sacc[g * D + tid] += h[(size_t)node * D + tid];
    }
    __syncthreads();
#pragma unroll
    for (int g = 0; g < G; g++) {
        float v = sacc[g * D + tid];
        if (v != 0.0f) atomicAdd(&g_sums[g * D + tid], v);
    }
}

// ---------------- final: mean -> linear -> softmax -----------------------------
__global__ __launch_bounds__(128)
void k_final(const float* __restrict__ Wl, const float* __restrict__ bl,
             float* __restrict__ out) {
    __shared__ float hg[G * D];
    __shared__ float logits[G * C];
    int tid = threadIdx.x;
#pragma unroll
    for (int g = 0; g < G; g++)
        hg[g * D + tid] = g_sums[g * D + tid] / fmaxf(g_counts[g], 1.0f);
    __syncthreads();
    if (tid < G * C) {
        int g = tid / C, c = tid % C;
        float acc = bl[c];
        for (int k = 0; k < D; k++) acc = fmaf(hg[g * D + k], Wl[k * C + c], acc);
        logits[tid] = acc;
    }
    __syncthreads();
    if (tid < G) {
        float m = -1e30f;
        for (int c = 0; c < C; c++) m = fmaxf(m, logits[tid * C + c]);
        float s = 0.0f;
        float e[C];
        for (int c = 0; c < C; c++) { e[c] = expf(logits[tid * C + c] - m); s += e[c]; }
        float inv = 1.0f / s;
        for (int c = 0; c < C; c++) out[tid * C + c] = e[c] * inv;
    }
}

// ---------------- launch --------------------------------------------------------
extern "C" void kernel_launch(void* const* d_in, const int* in_sizes, int n_in,
                              void* d_out, int out_size) {
    const float* x   = (const float*)d_in[0];
    const int*   ei  = (const int*)d_in[1];
    const int*   n2g = (const int*)d_in[2];
    const float* W1  = (const float*)d_in[3];
    const float* b1  = (const float*)d_in[4];
    const float* W2  = (const float*)d_in[5];
    const float* b2  = (const float*)d_in[6];
    const float* Wl  = (const float*)d_in[7];
    const float* bl  = (const float*)d_in[8];
    float* out = (float*)d_out;

    const int N = in_sizes[2];          // 50000
    const int E = in_sizes[1] / 2;      // 800000

    float* outq = nullptr; cudaGetSymbolAddress((void**)&outq, g_out_isqrt);
    float* inq  = nullptr; cudaGetSymbolAddress((void**)&inq,  g_in_isqrt);
    float* bufA = nullptr; cudaGetSymbolAddress((void**)&bufA, g_bufA);
    float* bufB = nullptr; cudaGetSymbolAddress((void**)&bufB, g_bufB);
    float* sums = nullptr; cudaGetSymbolAddress((void**)&sums, g_sums);
    float* cnts = nullptr; cudaGetSymbolAddress((void**)&cnts, g_counts);
    int* outc = nullptr; cudaGetSymbolAddress((void**)&outc, g_outcnt);
    int* inc  = nullptr; cudaGetSymbolAddress((void**)&inc,  g_incnt);
    int* rowp = nullptr; cudaGetSymbolAddress((void**)&rowp, g_rowptr);
    int* cur  = nullptr; cudaGetSymbolAddress((void**)&cur,  g_cursor);
    int* csr  = nullptr; cudaGetSymbolAddress((void**)&csr,  g_csr);
    int* bsum = nullptr; cudaGetSymbolAddress((void**)&bsum, g_bsums);

    const int nb = (N + 255) / 256;     // 196 <= 256

    // ---- CSR build + degree norms (once) ----
    k_zero_i2<<<nb, 256>>>(outc, inc, N);
    k_degcount<<<(E + 255) / 256, 256>>>(ei, E, outc, inc);
    k_scan1<<<nb, 256>>>(inc, N, bsum);
    k_scan2<<<1, 256>>>(bsum, nb, E, rowp, N);
    k_scan3<<<nb, 256>>>(inc, outc, N, bsum, rowp, cur, inq, outq);
    k_fill<<<(E + 255) / 256, 256>>>(ei, E, cur, csr);

    const int ntiles = (N + 127) / 128;
    const int gemmBlocks = 296;                       // 2 * 148 SMs, persistent
    const int gatherBlocks = (N * 32 + 255) / 256;    // 1 warp per row

    // layer 1: h1 = relu( gather((x*oq)@W1) * iq + b1 )
    k_gemm_rs<<<gemmBlocks, 256>>>(x, outq, W1, bufA, N, ntiles);
    k_gather<<<gatherBlocks, 256>>>(csr, rowp, bufA, inq, b1, bufB, N);

    // layer 2
    k_gemm_rs<<<gemmBlocks, 256>>>(bufB, outq, W2, bufA, N, ntiles);
    k_gather<<<gatherBlocks, 256>>>(csr, rowp, bufA, inq, b2, bufB, N);

    // pooling + head
    k_zero_f<<<4, 256>>>(sums, G * D);
    k_zero_f<<<1, 32>>>(cnts, G);
    k_counts<<<nb, 256>>>(n2g, N);
    k_pool<<<nb, 128>>>(bufB, n2g, N);
    k_final<<<1, 128>>>(Wl, bl, out);
}

// round 5
// speedup vs baseline: 1.6628x; 1.2034x over previous
#include <cuda_runtime.h>
#include <cuda_fp16.h>

#define NN 50000
#define EE 800000
#define D  128
#define G  8
#define C  10

// ---------------- scratch (static device globals; no allocs allowed) --------
__device__ float  g_out_isqrt[NN];
__device__ float  g_in_isqrt[NN];
__device__ __half g_h16A[NN * D];
__device__ __half g_h16B[NN * D];
__device__ float  g_sums[G * D];
__device__ float  g_counts[G];
__device__ int    g_outcnt[NN];
__device__ int    g_incnt[NN];
__device__ int    g_rowptr[NN + 1];
__device__ int    g_cursor[NN];
__device__ int    g_csr[EE];
__device__ int    g_bsums[256];

// ---------------- zero both degree arrays -------------------------------------
__global__ void k_zero_i2(int* a, int* b, int n) {
    int i = blockIdx.x * blockDim.x + threadIdx.x;
    if (i < n) { a[i] = 0; b[i] = 0; }
}

// ---------------- degree histograms (int) ------------------------------------
__global__ void k_degcount(const int* __restrict__ ei, int E,
                           int* __restrict__ outc, int* __restrict__ inc) {
    int e = blockIdx.x * blockDim.x + threadIdx.x;
    if (e < E) {
        atomicAdd(&outc[ei[e]], 1);
        atomicAdd(&inc[ei[E + e]], 1);
    }
}

// ---------------- out_isqrt + zero pooling accumulators ------------------------
__global__ void k_out_isqrt(const int* __restrict__ outc, float* __restrict__ oq,
                            int n, float* __restrict__ sums, float* __restrict__ cnts) {
    int i = blockIdx.x * blockDim.x + threadIdx.x;
    if (i < n) oq[i] = rsqrtf((float)max(outc[i], 1));
    if (i < G * D) sums[i] = 0.0f;
    if (i < G) cnts[i] = 0.0f;
}

// ---------------- parallel coalesced scan (3 passes) --------------------------
__device__ __forceinline__ int warp_incl_scan(int v, int lane) {
#pragma unroll
    for (int o = 1; o < 32; o <<= 1) {
        int t = __shfl_up_sync(0xffffffffu, v, o);
        if (lane >= o) v += t;
    }
    return v;
}

__device__ __forceinline__ int block_incl_scan(int v, int tid, int* ws) {
    int lane = tid & 31, wid = tid >> 5;
    int s = warp_incl_scan(v, lane);
    if (lane == 31) ws[wid] = s;
    __syncthreads();
    if (wid == 0) {
        int t = (lane < 8) ? ws[lane] : 0;
        t = warp_incl_scan(t, lane);
        if (lane < 8) ws[lane] = t;
    }
    __syncthreads();
    return s + (wid > 0 ? ws[wid - 1] : 0);
}

__global__ __launch_bounds__(256)
void k_scan1(const int* __restrict__ inc, int n, int* __restrict__ bsums) {
    __shared__ int ws[8];
    int tid = threadIdx.x;
    int i = blockIdx.x * 256 + tid;
    int v = (i < n) ? inc[i] : 0;
    int incl = block_incl_scan(v, tid, ws);
    if (tid == 255) bsums[blockIdx.x] = incl;
}

__global__ __launch_bounds__(256)
void k_scan2(int* __restrict__ bsums, int nb, int E, int* __restrict__ rowp, int n) {
    __shared__ int ws[8];
    int tid = threadIdx.x;
    int v = (tid < nb) ? bsums[tid] : 0;
    int incl = block_incl_scan(v, tid, ws);
    if (tid < nb) bsums[tid] = incl - v;
    if (tid == 0) rowp[n] = E;
}

// pass 3: also fold per-graph node counting (n2g) in here
__global__ __launch_bounds__(256)
void k_scan3(const int* __restrict__ inc, int n,
             const int* __restrict__ bsums, int* __restrict__ rowp,
             int* __restrict__ cur, float* __restrict__ iq,
             const int* __restrict__ n2g, float* __restrict__ cnts) {
    __shared__ int ws[8];
    int tid = threadIdx.x;
    int i = blockIdx.x * 256 + tid;
    int v = (i < n) ? inc[i] : 0;
    int incl = block_incl_scan(v, tid, ws);
    if (i < n) {
        int ex = incl - v + bsums[blockIdx.x];
        rowp[i] = ex;
        cur[i] = ex;
        iq[i] = rsqrtf((float)max(v, 1));
        atomicAdd(&cnts[n2g[i]], 1.0f);
    }
}

// ---------------- CSR fill: bucket src indices by dst -------------------------
__global__ void k_fill(const int* __restrict__ ei, int E,
                       int* __restrict__ cur, int* __restrict__ csr) {
    int e = blockIdx.x * blockDim.x + threadIdx.x;
    if (e < E) {
        int d = ei[E + e];
        int pos = atomicAdd(&cur[d], 1);
        csr[pos] = ei[e];
    }
}

// ---------------- packed f32x2 helpers -----------------------------------------
__device__ __forceinline__ unsigned long long pack_dup(float a) {
    unsigned long long r;
    unsigned u = __float_as_uint(a);
    asm("mov.b64 %0, {%1, %1};" : "=l"(r) : "r"(u));
    return r;
}
__device__ __forceinline__ void fma_x2(unsigned long long& acc,
                                       unsigned long long a,
                                       unsigned long long b) {
    asm("fma.rn.f32x2 %0, %1, %2, %0;" : "+l"(acc) : "l"(a), "l"(b));
}
__device__ __forceinline__ float2 unpack_x2(unsigned long long v) {
    unsigned lo, hi;
    asm("mov.b64 {%0, %1}, %2;" : "=r"(lo), "=r"(hi) : "l"(v));
    return make_float2(__uint_as_float(lo), __uint_as_float(hi));
}

// ---------------- GEMM: Cm[r, :] = (A[r, :] * rs[r]) @ W  (K = 128) ----------
// 128x128 tile, BK=8, 256 threads, 8x8/thread via f32x2. Output fp16.
template <typename TIn>
__global__ __launch_bounds__(256)
void k_gemm_rs(const TIn* __restrict__ A, const float* __restrict__ rs,
               const float* __restrict__ W, __half* __restrict__ Cm,
               int nrows, int ntiles) {
    __shared__ float As[8 * 128];
    __shared__ float Ws[8 * 128];
    const int tid = threadIdx.x;
    const int tx = tid & 15;
    const int ty = tid >> 4;
    const int arow = tid >> 1;
    const int aq   = (tid & 1) * 4;
    const int wk = tid >> 5;
    const int wc = (tid & 31) * 4;

    for (int tile = blockIdx.x; tile < ntiles; tile += gridDim.x) {
        const int rowBase = tile * 128;
        const int grow = rowBase + arow;
        const bool arow_ok = (grow < nrows);
        const float scale = arow_ok ? rs[grow] : 0.0f;
        const TIn* Arow = A + (size_t)grow * D;

        unsigned long long acc2[8][4];
#pragma unroll
        for (int i = 0; i < 8; i++)
#pragma unroll
            for (int j = 0; j < 4; j++) acc2[i][j] = 0ull;

        for (int k0 = 0; k0 < D; k0 += 8) {
            float av[4] = {0.f, 0.f, 0.f, 0.f};
            if (arow_ok) {
                if constexpr (sizeof(TIn) == 4) {
                    float4 t = *(const float4*)((const float*)Arow + k0 + aq);
                    av[0] = t.x; av[1] = t.y; av[2] = t.z; av[3] = t.w;
                } else {
                    uint2 raw = *(const uint2*)((const __half*)Arow + k0 + aq);
                    __half2 h0 = *(__half2*)&raw.x;
                    __half2 h1 = *(__half2*)&raw.y;
                    float2 f0 = __half22float2(h0);
                    float2 f1 = __half22float2(h1);
                    av[0] = f0.x; av[1] = f0.y; av[2] = f1.x; av[3] = f1.y;
                }
            }
            As[(aq + 0) * 128 + arow] = av[0] * scale;
            As[(aq + 1) * 128 + arow] = av[1] * scale;
            As[(aq + 2) * 128 + arow] = av[2] * scale;
            As[(aq + 3) * 128 + arow] = av[3] * scale;
            *(float4*)(Ws + wk * 128 + wc) =
                *(const float4*)(W + (size_t)(k0 + wk) * D + wc);
            __syncthreads();

#pragma unroll
            for (int kk = 0; kk < 8; kk++) {
                float am[8];
                *(float4*)(am)     = *(const float4*)(As + kk * 128 + ty * 8);
                *(float4*)(am + 4) = *(const float4*)(As + kk * 128 + ty * 8 + 4);
                ulonglong2 w01 = *(const ulonglong2*)(Ws + kk * 128 + tx * 8);
                ulonglong2 w23 = *(const ulonglong2*)(Ws + kk * 128 + tx * 8 + 4);
                unsigned long long wn2[4] = {w01.x, w01.y, w23.x, w23.y};
#pragma unroll
                for (int i = 0; i < 8; i++) {
                    unsigned long long a2 = pack_dup(am[i]);
#pragma unroll
                    for (int j = 0; j < 4; j++) fma_x2(acc2[i][j], a2, wn2[j]);
                }
            }
            __syncthreads();
        }

#pragma unroll
        for (int i = 0; i < 8; i++) {
            int r = rowBase + ty * 8 + i;
            if (r < nrows) {
                __half2 o[4];
#pragma unroll
                for (int j = 0; j < 4; j++)
                    o[j] = __float22half2_rn(unpack_x2(acc2[i][j]));
                *(uint4*)(Cm + (size_t)r * D + tx * 8) = *(uint4*)o;
            }
        }
        __syncthreads();
    }
}

// ---------------- gather + fused epilogue (fp16 in / fp16 out) ----------------
__global__ __launch_bounds__(256)
void k_gather(const int* __restrict__ csr, const int* __restrict__ rowp,
              const __half* __restrict__ A, const float* __restrict__ isq,
              const float* __restrict__ b, __half* __restrict__ out, int n) {
    int w = (blockIdx.x * blockDim.x + threadIdx.x) >> 5;
    if (w >= n) return;
    int lane = threadIdx.x & 31;
    int s0 = rowp[w], s1 = rowp[w + 1];
    float4 acc = make_float4(0.f, 0.f, 0.f, 0.f);
    const unsigned FULL = 0xffffffffu;
    int col = lane * 4;

    for (int base = s0; base < s1; base += 32) {
        int cnt = min(32, s1 - base);
        int myidx = (lane < cnt) ? csr[base + lane] : 0;
        int t = 0;
        for (; t + 4 <= cnt; t += 4) {
            int i0 = __shfl_sync(FULL, myidx, t + 0);
            int i1 = __shfl_sync(FULL, myidx, t + 1);
            int i2 = __shfl_sync(FULL, myidx, t + 2);
            int i3 = __shfl_sync(FULL, myidx, t + 3);
            uint2 r0 = *(const uint2*)(A + (size_t)i0 * D + col);
            uint2 r1 = *(const uint2*)(A + (size_t)i1 * D + col);
            uint2 r2 = *(const uint2*)(A + (size_t)i2 * D + col);
            uint2 r3 = *(const uint2*)(A + (size_t)i3 * D + col);
            float2 a0 = __half22float2(*(__half2*)&r0.x), b0 = __half22float2(*(__half2*)&r0.y);
            float2 a1 = __half22float2(*(__half2*)&r1.x), b1 = __half22float2(*(__half2*)&r1.y);
            float2 a2 = __half22float2(*(__half2*)&r2.x), b2 = __half22float2(*(__half2*)&r2.y);
            float2 a3 = __half22float2(*(__half2*)&r3.x), b3 = __half22float2(*(__half2*)&r3.y);
            acc.x += (a0.x + a1.x) + (a2.x + a3.x);
            acc.y += (a0.y + a1.y) + (a2.y + a3.y);
            acc.z += (b0.x + b1.x) + (b2.x + b3.x);
            acc.w += (b0.y + b1.y) + (b2.y + b3.y);
        }
        for (; t < cnt; t++) {
            int s = __shfl_sync(FULL, myidx, t);
            uint2 r = *(const uint2*)(A + (size_t)s * D + col);
            float2 a = __half22float2(*(__half2*)&r.x);
            float2 bb = __half22float2(*(__half2*)&r.y);
            acc.x += a.x; acc.y += a.y; acc.z += bb.x; acc.w += bb.y;
        }
    }

    float sc = isq[w];
    float4 bb = *(const float4*)(b + col);
    float2 r0, r1;
    r0.x = fmaxf(fmaf(acc.x, sc, bb.x), 0.0f);
    r0.y = fmaxf(fmaf(acc.y, sc, bb.y), 0.0f);
    r1.x = fmaxf(fmaf(acc.z, sc, bb.z), 0.0f);
    r1.y = fmaxf(fmaf(acc.w, sc, bb.w), 0.0f);
    __half2 o[2] = {__float22half2_rn(r0), __float22half2_rn(r1)};
    *(uint2*)(out + (size_t)w * D + col) = *(uint2*)o;
}

// ---------------- pooling: per-graph feature sums (fp16 input) -----------------
// 64 nodes per block, 128 threads (one per dim), register accumulation.
__global__ __launch_bounds__(128)
void k_pool(const __half* __restrict__ h, const int* __restrict__ n2g, int n) {
    int tid = threadIdx.x;
    int base = blockIdx.x * 64;
    int end = min(base + 64, n);
    if (base >= n) return;
    int curg = n2g[base];
    float acc = 0.0f;
    for (int node = base; node < end; node++) {
        int g = n2g[node];
        if (g != curg) {
            atomicAdd(&g_sums[curg * D + tid], acc);
            curg = g;
            acc = 0.0f;
        }
        acc += __half2float(h[(size_t)node * D + tid]);
    }
    atomicAdd(&g_sums[curg * D + tid], acc);
}

// ---------------- final: mean -> linear -> softmax -----------------------------
__global__ __launch_bounds__(128)
void k_final(const float* __restrict__ Wl, const float* __restrict__ bl,
             float* __restrict__ out) {
    __shared__ float hg[G * D];
    __shared__ float logits[G * C];
    int tid = threadIdx.x;
#pragma unroll
    for (int g = 0; g < G; g++)
        hg[g * D + tid] = g_sums[g * D + tid] / fmaxf(g_counts[g], 1.0f);
    __syncthreads();
    if (tid < G * C) {
        int g = tid / C, c = tid % C;
        float acc = bl[c];
        for (int k = 0; k < D; k++) acc = fmaf(hg[g * D + k], Wl[k * C + c], acc);
        logits[tid] = acc;
    }
    __syncthreads();
    if (tid < G) {
        float m = -1e30f;
        for (int c = 0; c < C; c++) m = fmaxf(m, logits[tid * C + c]);
        float s = 0.0f;
        float e[C];
        for (int c = 0; c < C; c++) { e[c] = expf(logits[tid * C + c] - m); s += e[c]; }
        float inv = 1.0f / s;
        for (int c = 0; c < C; c++) out[tid * C + c] = e[c] * inv;
    }
}

// ---------------- launch --------------------------------------------------------
extern "C" void kernel_launch(void* const* d_in, const int* in_sizes, int n_in,
                              void* d_out, int out_size) {
    const float* x   = (const float*)d_in[0];
    const int*   ei  = (const int*)d_in[1];
    const int*   n2g = (const int*)d_in[2];
    const float* W1  = (const float*)d_in[3];
    const float* b1  = (const float*)d_in[4];
    const float* W2  = (const float*)d_in[5];
    const float* b2  = (const float*)d_in[6];
    const float* Wl  = (const float*)d_in[7];
    const float* bl  = (const float*)d_in[8];
    float* out = (float*)d_out;

    const int N = in_sizes[2];          // 50000
    const int E = in_sizes[1] / 2;      // 800000

    float* outq = nullptr; cudaGetSymbolAddress((void**)&outq, g_out_isqrt);
    float* inq  = nullptr; cudaGetSymbolAddress((void**)&inq,  g_in_isqrt);
    __half* hA  = nullptr; cudaGetSymbolAddress((void**)&hA, g_h16A);
    __half* hB  = nullptr; cudaGetSymbolAddress((void**)&hB, g_h16B);
    float* sums = nullptr; cudaGetSymbolAddress((void**)&sums, g_sums);
    float* cnts = nullptr; cudaGetSymbolAddress((void**)&cnts, g_counts);
    int* outc = nullptr; cudaGetSymbolAddress((void**)&outc, g_outcnt);
    int* inc  = nullptr; cudaGetSymbolAddress((void**)&inc,  g_incnt);
    int* rowp = nullptr; cudaGetSymbolAddress((void**)&rowp, g_rowptr);
    int* cur  = nullptr; cudaGetSymbolAddress((void**)&cur,  g_cursor);
    int* csr  = nullptr; cudaGetSymbolAddress((void**)&csr,  g_csr);
    int* bsum = nullptr; cudaGetSymbolAddress((void**)&bsum, g_bsums);

    const int nb = (N + 255) / 256;     // 196 <= 256
    const int ntiles = (N + 127) / 128;
    const int gemmBlocks = 296;
    const int gatherBlocks = (N * 32 + 255) / 256;

    // launches 0..2: degree norms (and zero pooling accumulators)
    k_zero_i2<<<nb, 256>>>(outc, inc, N);
    k_degcount<<<(E + 255) / 256, 256>>>(ei, E, outc, inc);
    k_out_isqrt<<<nb, 256>>>(outc, outq, N, sums, cnts);

    // launch 3 (profiled slot): layer-1 GEMM  h = (x*oq) @ W1  -> fp16
    k_gemm_rs<float><<<gemmBlocks, 256>>>(x, outq, W1, hA, N, ntiles);

    // launches 4..7: CSR build (+ per-graph counts folded into scan3)
    k_scan1<<<nb, 256>>>(inc, N, bsum);
    k_scan2<<<1, 256>>>(bsum, nb, E, rowp, N);
    k_scan3<<<nb, 256>>>(inc, N, bsum, rowp, cur, inq, n2g, cnts);
    k_fill<<<(E + 255) / 256, 256>>>(ei, E, cur, csr);

    // layer 1 gather, layer 2
    k_gather<<<gatherBlocks, 256>>>(csr, rowp, hA, inq, b1, hB, N);
    k_gemm_rs<__half><<<gemmBlocks, 256>>>(hB, outq, W2, hA, N, ntiles);
    k_gather<<<gatherBlocks, 256>>>(csr, rowp, hA, inq, b2, hB, N);

    // pooling + head
    k_pool<<<(N + 63) / 64, 128>>>(hB, n2g, N);
    k_final<<<1, 128>>>(Wl, bl, out);
}

// round 6
// speedup vs baseline: 2.0268x; 1.2189x over previous
#include <cuda_runtime.h>
#include <cuda_fp16.h>

#define NN 50000
#define EE 800000
#define D  128
#define G  8
#define C  10

// ---------------- scratch (static device globals; no allocs allowed) --------
__device__ float  g_out_isqrt[NN];
__device__ float  g_in_isqrt[NN];
__device__ __half g_x16[NN * D];
__device__ __half g_h16A[NN * D];
__device__ __half g_h16B[NN * D];
__device__ __half g_W1hi[D * D];
__device__ __half g_W1lo[D * D];
__device__ __half g_W2hi[D * D];
__device__ __half g_W2lo[D * D];
__device__ float  g_sums[G * D];
__device__ float  g_counts[G];
__device__ int    g_outcnt[NN];
__device__ int    g_incnt[NN];
__device__ int    g_rowptr[NN + 1];
__device__ int    g_cursor[NN];
__device__ int    g_csr[EE];
__device__ int    g_bsums[256];

// ---------------- zero both degree arrays -------------------------------------
__global__ void k_zero_i2(int* a, int* b, int n) {
    int i = blockIdx.x * blockDim.x + threadIdx.x;
    if (i < n) { a[i] = 0; b[i] = 0; }
}

// ---------------- degree histograms (int) ------------------------------------
__global__ void k_degcount(const int* __restrict__ ei, int E,
                           int* __restrict__ outc, int* __restrict__ inc) {
    int e = blockIdx.x * blockDim.x + threadIdx.x;
    if (e < E) {
        atomicAdd(&outc[ei[e]], 1);
        atomicAdd(&inc[ei[E + e]], 1);
    }
}

// ---------------- out_isqrt + zero pooling accumulators ------------------------
__global__ void k_out_isqrt(const int* __restrict__ outc, float* __restrict__ oq,
                            int n, float* __restrict__ sums, float* __restrict__ cnts) {
    int i = blockIdx.x * blockDim.x + threadIdx.x;
    if (i < n) oq[i] = rsqrtf((float)max(outc[i], 1));
    if (i < G * D) sums[i] = 0.0f;
    if (i < G) cnts[i] = 0.0f;
}

// ---------------- x16 = fp16(x * oq[row]) --------------------------------------
__global__ void k_xconv(const float* __restrict__ x, const float* __restrict__ oq,
                        __half* __restrict__ x16, int n) {
    int i4 = blockIdx.x * blockDim.x + threadIdx.x;   // one float4 (4 elems)
    int total = n * (D / 4);
    if (i4 >= total) return;
    int r = i4 >> 5;                                  // 32 float4 per row
    float s = oq[r];
    float4 v = *(const float4*)(x + (size_t)i4 * 4);
    __half2 o[2];
    o[0] = __floats2half2_rn(v.x * s, v.y * s);
    o[1] = __floats2half2_rn(v.z * s, v.w * s);
    *(uint2*)(x16 + (size_t)i4 * 4) = *(uint2*)o;
}

// ---------------- W -> transposed fp16 hi/lo pair -------------------------------
// W given [k][n] row-major; write Wt[n][k] hi and lo.
__global__ void k_wconv(const float* __restrict__ W1, const float* __restrict__ W2,
                        __half* __restrict__ w1h, __half* __restrict__ w1l,
                        __half* __restrict__ w2h, __half* __restrict__ w2l) {
    int i = blockIdx.x * blockDim.x + threadIdx.x;
    if (i >= D * D) return;
    int k = i >> 7, n = i & 127;
    {
        float v = W1[i];
        __half hi = __float2half_rn(v);
        __half lo = __float2half_rn(v - __half2float(hi));
        w1h[n * D + k] = hi; w1l[n * D + k] = lo;
    }
    {
        float v = W2[i];
        __half hi = __float2half_rn(v);
        __half lo = __float2half_rn(v - __half2float(hi));
        w2h[n * D + k] = hi; w2l[n * D + k] = lo;
    }
}

// ---------------- parallel coalesced scan (3 passes) --------------------------
__device__ __forceinline__ int warp_incl_scan(int v, int lane) {
#pragma unroll
    for (int o = 1; o < 32; o <<= 1) {
        int t = __shfl_up_sync(0xffffffffu, v, o);
        if (lane >= o) v += t;
    }
    return v;
}

__device__ __forceinline__ int block_incl_scan(int v, int tid, int* ws) {
    int lane = tid & 31, wid = tid >> 5;
    int s = warp_incl_scan(v, lane);
    if (lane == 31) ws[wid] = s;
    __syncthreads();
    if (wid == 0) {
        int t = (lane < 8) ? ws[lane] : 0;
        t = warp_incl_scan(t, lane);
        if (lane < 8) ws[lane] = t;
    }
    __syncthreads();
    return s + (wid > 0 ? ws[wid - 1] : 0);
}

__global__ __launch_bounds__(256)
void k_scan1(const int* __restrict__ inc, int n, int* __restrict__ bsums) {
    __shared__ int ws[8];
    int tid = threadIdx.x;
    int i = blockIdx.x * 256 + tid;
    int v = (i < n) ? inc[i] : 0;
    int incl = block_incl_scan(v, tid, ws);
    if (tid == 255) bsums[blockIdx.x] = incl;
}

__global__ __launch_bounds__(256)
void k_scan2(int* __restrict__ bsums, int nb, int E, int* __restrict__ rowp, int n) {
    __shared__ int ws[8];
    int tid = threadIdx.x;
    int v = (tid < nb) ? bsums[tid] : 0;
    int incl = block_incl_scan(v, tid, ws);
    if (tid < nb) bsums[tid] = incl - v;
    if (tid == 0) rowp[n] = E;
}

__global__ __launch_bounds__(256)
void k_scan3(const int* __restrict__ inc, int n,
             const int* __restrict__ bsums, int* __restrict__ rowp,
             int* __restrict__ cur, float* __restrict__ iq,
             const int* __restrict__ n2g, float* __restrict__ cnts) {
    __shared__ int ws[8];
    int tid = threadIdx.x;
    int i = blockIdx.x * 256 + tid;
    int v = (i < n) ? inc[i] : 0;
    int incl = block_incl_scan(v, tid, ws);
    if (i < n) {
        int ex = incl - v + bsums[blockIdx.x];
        rowp[i] = ex;
        cur[i] = ex;
        iq[i] = rsqrtf((float)max(v, 1));
        atomicAdd(&cnts[n2g[i]], 1.0f);
    }
}

// ---------------- CSR fill: bucket src indices by dst -------------------------
__global__ void k_fill(const int* __restrict__ ei, int E,
                       int* __restrict__ cur, int* __restrict__ csr) {
    int e = blockIdx.x * blockDim.x + threadIdx.x;
    if (e < E) {
        int d = ei[E + e];
        int pos = atomicAdd(&cur[d], 1);
        csr[pos] = ei[e];
    }
}

// ---------------- tensor-core GEMM: Cm = A @ (Whi + Wlo), fp16 in/out ---------
// 128x128 tile, 256 threads, 8 warps each 32x64, W resident in smem.
__device__ __forceinline__ void mma16816(float* c, const unsigned* a,
                                         unsigned b0, unsigned b1) {
    asm volatile(
        "mma.sync.aligned.m16n8k16.row.col.f32.f16.f16.f32 "
        "{%0,%1,%2,%3}, {%4,%5,%6,%7}, {%8,%9}, {%0,%1,%2,%3};"
        : "+f"(c[0]), "+f"(c[1]), "+f"(c[2]), "+f"(c[3])
        : "r"(a[0]), "r"(a[1]), "r"(a[2]), "r"(a[3]), "r"(b0), "r"(b1));
}

#define LDA 136   // padded smem stride in halves

__global__ __launch_bounds__(256)
void k_gemm_tc(const __half* __restrict__ A, const __half* __restrict__ Whi,
               const __half* __restrict__ Wlo, __half* __restrict__ Cm,
               int nrows, int ntiles) {
    extern __shared__ __half sm[];
    __half* As = sm;                    // 128 x LDA
    __half* Bh = sm + 128 * LDA;        // 128 x LDA  (Wt hi, [n][k])
    __half* Bl = Bh + 128 * LDA;        // 128 x LDA  (Wt lo)

    const int tid = threadIdx.x;
    const int wid = tid >> 5, lane = tid & 31;
    const int wr = wid >> 1;            // 0..3 row group (32 rows)
    const int wc = wid & 1;             // 0..1 col group (64 cols)
    const int g = lane >> 2, tg = lane & 3;

    // load Wt hi/lo into smem once
    for (int j = tid; j < 2048; j += 256) {
        int n = j >> 4, kc = (j & 15) * 8;
        *(uint4*)(Bh + n * LDA + kc) = *(const uint4*)(Whi + n * D + kc);
        *(uint4*)(Bl + n * LDA + kc) = *(const uint4*)(Wlo + n * D + kc);
    }

    for (int tile = blockIdx.x; tile < ntiles; tile += gridDim.x) {
        const int rowBase = tile * 128;
        __syncthreads();   // protect As from previous iteration's readers
        // load A tile (zero-fill past nrows)
        for (int j = tid; j < 2048; j += 256) {
            int r = j >> 4, kc = (j & 15) * 8;
            int gr = rowBase + r;
            uint4 v = make_uint4(0u, 0u, 0u, 0u);
            if (gr < nrows) v = *(const uint4*)(A + (size_t)gr * D + kc);
            *(uint4*)(As + r * LDA + kc) = v;
        }
        __syncthreads();

        float acc[2][8][4];
#pragma unroll
        for (int mt = 0; mt < 2; mt++)
#pragma unroll
            for (int nt = 0; nt < 8; nt++)
#pragma unroll
                for (int q = 0; q < 4; q++) acc[mt][nt][q] = 0.0f;

#pragma unroll
        for (int ks = 0; ks < 8; ks++) {
            const int k0 = ks * 16;
            unsigned a[2][4];
#pragma unroll
            for (int mt = 0; mt < 2; mt++) {
                const __half* pr = As + (wr * 32 + mt * 16 + g) * LDA + k0 + tg * 2;
                a[mt][0] = *(const unsigned*)(pr);
                a[mt][1] = *(const unsigned*)(pr + 8 * LDA);
                a[mt][2] = *(const unsigned*)(pr + 8);
                a[mt][3] = *(const unsigned*)(pr + 8 * LDA + 8);
            }
#pragma unroll
            for (int nt = 0; nt < 8; nt++) {
                const int n = wc * 64 + nt * 8 + g;
                const __half* ph = Bh + n * LDA + k0 + tg * 2;
                const __half* pl = Bl + n * LDA + k0 + tg * 2;
                unsigned bh0 = *(const unsigned*)(ph);
                unsigned bh1 = *(const unsigned*)(ph + 8);
                unsigned bl0 = *(const unsigned*)(pl);
                unsigned bl1 = *(const unsigned*)(pl + 8);
#pragma unroll
                for (int mt = 0; mt < 2; mt++) {
                    mma16816(acc[mt][nt], a[mt], bh0, bh1);
                    mma16816(acc[mt][nt], a[mt], bl0, bl1);
                }
            }
        }

        // epilogue: fp16 stores
#pragma unroll
        for (int mt = 0; mt < 2; mt++) {
            int r0 = rowBase + wr * 32 + mt * 16 + g;
            int r1 = r0 + 8;
#pragma unroll
            for (int nt = 0; nt < 8; nt++) {
                int col = wc * 64 + nt * 8 + tg * 2;
                if (r0 < nrows)
                    *(__half2*)(Cm + (size_t)r0 * D + col) =
                        __floats2half2_rn(acc[mt][nt][0], acc[mt][nt][1]);
                if (r1 < nrows)
                    *(__half2*)(Cm + (size_t)r1 * D + col) =
                        __floats2half2_rn(acc[mt][nt][2], acc[mt][nt][3]);
            }
        }
    }
}

// ---------------- gather + fused epilogue (fp16 in / fp16 out) ----------------
// scale_oq != 0: output additionally scaled by oq[w] (feeds next GEMM).
__global__ __launch_bounds__(256)
void k_gather(const int* __restrict__ csr, const int* __restrict__ rowp,
              const __half* __restrict__ A, const float* __restrict__ isq,
              const float* __restrict__ b, const float* __restrict__ oq,
              int scale_oq, __half* __restrict__ out, int n) {
    int w = (blockIdx.x * blockDim.x + threadIdx.x) >> 5;
    if (w >= n) return;
    int lane = threadIdx.x & 31;
    int s0 = rowp[w], s1 = rowp[w + 1];
    float4 acc = make_float4(0.f, 0.f, 0.f, 0.f);
    const unsigned FULL = 0xffffffffu;
    int col = lane * 4;

    for (int base = s0; base < s1; base += 32) {
        int cnt = min(32, s1 - base);
        int myidx = (lane < cnt) ? csr[base + lane] : 0;
        int t = 0;
        for (; t + 4 <= cnt; t += 4) {
            int i0 = __shfl_sync(FULL, myidx, t + 0);
            int i1 = __shfl_sync(FULL, myidx, t + 1);
            int i2 = __shfl_sync(FULL, myidx, t + 2);
            int i3 = __shfl_sync(FULL, myidx, t + 3);
            uint2 r0 = *(const uint2*)(A + (size_t)i0 * D + col);
            uint2 r1 = *(const uint2*)(A + (size_t)i1 * D + col);
            uint2 r2 = *(const uint2*)(A + (size_t)i2 * D + col);
            uint2 r3 = *(const uint2*)(A + (size_t)i3 * D + col);
            float2 a0 = __half22float2(*(__half2*)&r0.x), b0 = __half22float2(*(__half2*)&r0.y);
            float2 a1 = __half22float2(*(__half2*)&r1.x), b1 = __half22float2(*(__half2*)&r1.y);
            float2 a2 = __half22float2(*(__half2*)&r2.x), b2 = __half22float2(*(__half2*)&r2.y);
            float2 a3 = __half22float2(*(__half2*)&r3.x), b3 = __half22float2(*(__half2*)&r3.y);
            acc.x += (a0.x + a1.x) + (a2.x + a3.x);
            acc.y += (a0.y + a1.y) + (a2.y + a3.y);
            acc.z += (b0.x + b1.x) + (b2.x + b3.x);
            acc.w += (b0.y + b1.y) + (b2.y + b3.y);
        }
        for (; t < cnt; t++) {
            int s = __shfl_sync(FULL, myidx, t);
            uint2 r = *(const uint2*)(A + (size_t)s * D + col);
            float2 a = __half22float2(*(__half2*)&r.x);
            float2 bb = __half22float2(*(__half2*)&r.y);
            acc.x += a.x; acc.y += a.y; acc.z += bb.x; acc.w += bb.y;
        }
    }

    float sc = isq[w];
    float post = scale_oq ? oq[w] : 1.0f;
    float4 bb = *(const float4*)(b + col);
    float2 r0, r1;
    r0.x = fmaxf(fmaf(acc.x, sc, bb.x), 0.0f) * post;
    r0.y = fmaxf(fmaf(acc.y, sc, bb.y), 0.0f) * post;
    r1.x = fmaxf(fmaf(acc.z, sc, bb.z), 0.0f) * post;
    r1.y = fmaxf(fmaf(acc.w, sc, bb.w), 0.0f) * post;
    __half2 o[2] = {__float22half2_rn(r0), __float22half2_rn(r1)};
    *(uint2*)(out + (size_t)w * D + col) = *(uint2*)o;
}

// ---------------- pooling: per-graph feature sums (fp16 input) -----------------
__global__ __launch_bounds__(128)
void k_pool(const __half* __restrict__ h, const int* __restrict__ n2g, int n) {
    int tid = threadIdx.x;
    int base = blockIdx.x * 64;
    int end = min(base + 64, n);
    if (base >= n) return;
    int curg = n2g[base];
    float acc = 0.0f;
    for (int node = base; node < end; node++) {
        int g = n2g[node];
        if (g != curg) {
            atomicAdd(&g_sums[curg * D + tid], acc);
            curg = g;
            acc = 0.0f;
        }
        acc += __half2float(h[(size_t)node * D + tid]);
    }
    atomicAdd(&g_sums[curg * D + tid], acc);
}

// ---------------- final: mean -> linear -> softmax -----------------------------
__global__ __launch_bounds__(128)
void k_final(const float* __restrict__ Wl, const float* __restrict__ bl,
             float* __restrict__ out) {
    __shared__ float hg[G * D];
    __shared__ float logits[G * C];
    int tid = threadIdx.x;
#pragma unroll
    for (int g = 0; g < G; g++)
        hg[g * D + tid] = g_sums[g * D + tid] / fmaxf(g_counts[g], 1.0f);
    __syncthreads();
    if (tid < G * C) {
        int g = tid / C, c = tid % C;
        float acc = bl[c];
        for (int k = 0; k < D; k++) acc = fmaf(hg[g * D + k], Wl[k * C + c], acc);
        logits[tid] = acc;
    }
    __syncthreads();
    if (tid < G) {
        float m = -1e30f;
        for (int c = 0; c < C; c++) m = fmaxf(m, logits[tid * C + c]);
        float s = 0.0f;
        float e[C];
        for (int c = 0; c < C; c++) { e[c] = expf(logits[tid * C + c] - m); s += e[c]; }
        float inv = 1.0f / s;
        for (int c = 0; c < C; c++) out[tid * C + c] = e[c] * inv;
    }
}

// ---------------- launch --------------------------------------------------------
extern "C" void kernel_launch(void* const* d_in, const int* in_sizes, int n_in,
                              void* d_out, int out_size) {
    const float* x   = (const float*)d_in[0];
    const int*   ei  = (const int*)d_in[1];
    const int*   n2g = (const int*)d_in[2];
    const float* W1  = (const float*)d_in[3];
    const float* b1  = (const float*)d_in[4];
    const float* W2  = (const float*)d_in[5];
    const float* b2  = (const float*)d_in[6];
    const float* Wl  = (const float*)d_in[7];
    const float* bl  = (const float*)d_in[8];
    float* out = (float*)d_out;

    const int N = in_sizes[2];          // 50000
    const int E = in_sizes[1] / 2;      // 800000

    float* outq = nullptr; cudaGetSymbolAddress((void**)&outq, g_out_isqrt);
    float* inq  = nullptr; cudaGetSymbolAddress((void**)&inq,  g_in_isqrt);
    __half* x16 = nullptr; cudaGetSymbolAddress((void**)&x16, g_x16);
    __half* hA  = nullptr; cudaGetSymbolAddress((void**)&hA, g_h16A);
    __half* hB  = nullptr; cudaGetSymbolAddress((void**)&hB, g_h16B);
    __half* w1h = nullptr; cudaGetSymbolAddress((void**)&w1h, g_W1hi);
    __half* w1l = nullptr; cudaGetSymbolAddress((void**)&w1l, g_W1lo);
    __half* w2h = nullptr; cudaGetSymbolAddress((void**)&w2h, g_W2hi);
    __half* w2l = nullptr; cudaGetSymbolAddress((void**)&w2l, g_W2lo);
    float* sums = nullptr; cudaGetSymbolAddress((void**)&sums, g_sums);
    float* cnts = nullptr; cudaGetSymbolAddress((void**)&cnts, g_counts);
    int* outc = nullptr; cudaGetSymbolAddress((void**)&outc, g_outcnt);
    int* inc  = nullptr; cudaGetSymbolAddress((void**)&inc,  g_incnt);
    int* rowp = nullptr; cudaGetSymbolAddress((void**)&rowp, g_rowptr);
    int* cur  = nullptr; cudaGetSymbolAddress((void**)&cur,  g_cursor);
    int* csr  = nullptr; cudaGetSymbolAddress((void**)&csr,  g_csr);
    int* bsum = nullptr; cudaGetSymbolAddress((void**)&bsum, g_bsums);

    const int nb = (N + 255) / 256;
    const int ntiles = (N + 127) / 128;
    const int gemmBlocks = 296;
    const int gatherBlocks = (N * 32 + 255) / 256;
    const int smemGemm = 3 * 128 * LDA * (int)sizeof(__half);   // 104448

    static int s_attr_done = 0;
    if (!s_attr_done) {
        cudaFuncSetAttribute(k_gemm_tc, cudaFuncAttributeMaxDynamicSharedMemorySize,
                             smemGemm);
        s_attr_done = 1;
    }

    // 0..2: degrees + norms (+ zero pooling accumulators)
    k_zero_i2<<<nb, 256>>>(outc, inc, N);
    k_degcount<<<(E + 255) / 256, 256>>>(ei, E, outc, inc);
    k_out_isqrt<<<nb, 256>>>(outc, outq, N, sums, cnts);

    // 3..4: fp16 conversions
    k_xconv<<<(N * 32 + 255) / 256, 256>>>(x, outq, x16, N);
    k_wconv<<<(D * D + 255) / 256, 256>>>(W1, W2, w1h, w1l, w2h, w2l);

    // 5: layer-1 GEMM (tensor cores)
    k_gemm_tc<<<gemmBlocks, 256, smemGemm>>>(x16, w1h, w1l, hA, N, ntiles);

    // 6..9: CSR build (+ per-graph counts folded into scan3)
    k_scan1<<<nb, 256>>>(inc, N, bsum);
    k_scan2<<<1, 256>>>(bsum, nb, E, rowp, N);
    k_scan3<<<nb, 256>>>(inc, N, bsum, rowp, cur, inq, n2g, cnts);
    k_fill<<<(E + 255) / 256, 256>>>(ei, E, cur, csr);

    // 10..12: gather1 (fold oq), GEMM2, gather2
    k_gather<<<gatherBlocks, 256>>>(csr, rowp, hA, inq, b1, outq, 1, hB, N);
    k_gemm_tc<<<gemmBlocks, 256, smemGemm>>>(hB, w2h, w2l, hA, N, ntiles);
    k_gather<<<gatherBlocks, 256>>>(csr, rowp, hA, inq, b2, outq, 0, hB, N);

    // 13..14: pooling + head
    k_pool<<<(N + 63) / 64, 128>>>(hB, n2g, N);
    k_final<<<1, 128>>>(Wl, bl, out);
}

// round 7
// speedup vs baseline: 2.1973x; 1.0841x over previous
#include <cuda_runtime.h>
#include <cuda_fp16.h>

#define NN 50000
#define EE 800000
#define D  128
#define G  8
#define C  10

// ---------------- scratch (static device globals; no allocs allowed) --------
__device__ float  g_out_isqrt[NN];
__device__ float  g_in_isqrt[NN];
__device__ __half g_h16A[NN * D];
__device__ __half g_h16B[NN * D];
__device__ __half g_W1hi[D * D];
__device__ __half g_W1lo[D * D];
__device__ __half g_W2hi[D * D];
__device__ __half g_W2lo[D * D];
__device__ float  g_sums[G * D];
__device__ float  g_counts[G];
__device__ int    g_outcnt[NN];
__device__ int    g_incnt[NN];
__device__ int    g_rowptr[NN + 1];
__device__ int    g_cursor[NN];
__device__ int    g_csr[EE];
__device__ int    g_bsums[256];

// ---------------- zero both degree arrays -------------------------------------
__global__ void k_zero_i2(int* a, int* b, int n) {
    int i = blockIdx.x * blockDim.x + threadIdx.x;
    if (i < n) { a[i] = 0; b[i] = 0; }
}

// ---------------- degree histograms (int) ------------------------------------
__global__ void k_degcount(const int* __restrict__ ei, int E,
                           int* __restrict__ outc, int* __restrict__ inc) {
    int e = blockIdx.x * blockDim.x + threadIdx.x;
    if (e < E) {
        atomicAdd(&outc[ei[e]], 1);
        atomicAdd(&inc[ei[E + e]], 1);
    }
}

// ---------------- out_isqrt + zero pooling accumulators ------------------------
__global__ void k_out_isqrt(const int* __restrict__ outc, float* __restrict__ oq,
                            int n, float* __restrict__ sums, float* __restrict__ cnts) {
    int i = blockIdx.x * blockDim.x + threadIdx.x;
    if (i < n) oq[i] = rsqrtf((float)max(outc[i], 1));
    if (i < G * D) sums[i] = 0.0f;
    if (i < G) cnts[i] = 0.0f;
}

// ---------------- W -> transposed fp16 hi/lo pair -------------------------------
__global__ void k_wconv(const float* __restrict__ W1, const float* __restrict__ W2,
                        __half* __restrict__ w1h, __half* __restrict__ w1l,
                        __half* __restrict__ w2h, __half* __restrict__ w2l) {
    int i = blockIdx.x * blockDim.x + threadIdx.x;
    if (i >= D * D) return;
    int k = i >> 7, n = i & 127;
    {
        float v = W1[i];
        __half hi = __float2half_rn(v);
        __half lo = __float2half_rn(v - __half2float(hi));
        w1h[n * D + k] = hi; w1l[n * D + k] = lo;
    }
    {
        float v = W2[i];
        __half hi = __float2half_rn(v);
        __half lo = __float2half_rn(v - __half2float(hi));
        w2h[n * D + k] = hi; w2l[n * D + k] = lo;
    }
}

// ---------------- parallel coalesced scan (3 passes) --------------------------
__device__ __forceinline__ int warp_incl_scan(int v, int lane) {
#pragma unroll
    for (int o = 1; o < 32; o <<= 1) {
        int t = __shfl_up_sync(0xffffffffu, v, o);
        if (lane >= o) v += t;
    }
    return v;
}

__device__ __forceinline__ int block_incl_scan(int v, int tid, int* ws) {
    int lane = tid & 31, wid = tid >> 5;
    int s = warp_incl_scan(v, lane);
    if (lane == 31) ws[wid] = s;
    __syncthreads();
    if (wid == 0) {
        int t = (lane < 8) ? ws[lane] : 0;
        t = warp_incl_scan(t, lane);
        if (lane < 8) ws[lane] = t;
    }
    __syncthreads();
    return s + (wid > 0 ? ws[wid - 1] : 0);
}

__global__ __launch_bounds__(256)
void k_scan1(const int* __restrict__ inc, int n, int* __restrict__ bsums) {
    __shared__ int ws[8];
    int tid = threadIdx.x;
    int i = blockIdx.x * 256 + tid;
    int v = (i < n) ? inc[i] : 0;
    int incl = block_incl_scan(v, tid, ws);
    if (tid == 255) bsums[blockIdx.x] = incl;
}

__global__ __launch_bounds__(256)
void k_scan2(int* __restrict__ bsums, int nb, int E, int* __restrict__ rowp, int n) {
    __shared__ int ws[8];
    int tid = threadIdx.x;
    int v = (tid < nb) ? bsums[tid] : 0;
    int incl = block_incl_scan(v, tid, ws);
    if (tid < nb) bsums[tid] = incl - v;
    if (tid == 0) rowp[n] = E;
}

__global__ __launch_bounds__(256)
void k_scan3(const int* __restrict__ inc, int n,
             const int* __restrict__ bsums, int* __restrict__ rowp,
             int* __restrict__ cur, float* __restrict__ iq,
             const int* __restrict__ n2g, float* __restrict__ cnts) {
    __shared__ int ws[8];
    int tid = threadIdx.x;
    int i = blockIdx.x * 256 + tid;
    int v = (i < n) ? inc[i] : 0;
    int incl = block_incl_scan(v, tid, ws);
    if (i < n) {
        int ex = incl - v + bsums[blockIdx.x];
        rowp[i] = ex;
        cur[i] = ex;
        iq[i] = rsqrtf((float)max(v, 1));
        atomicAdd(&cnts[n2g[i]], 1.0f);
    }
}

// ---------------- CSR fill: bucket src indices by dst -------------------------
__global__ void k_fill(const int* __restrict__ ei, int E,
                       int* __restrict__ cur, int* __restrict__ csr) {
    int e = blockIdx.x * blockDim.x + threadIdx.x;
    if (e < E) {
        int d = ei[E + e];
        int pos = atomicAdd(&cur[d], 1);
        csr[pos] = ei[e];
    }
}

// ---------------- tensor-core GEMM: Cm = A @ (Whi + Wlo), fp16 out ------------
// TIn=float: A converted + scaled by rs[row] during smem load (fused xconv).
__device__ __forceinline__ void mma16816(float* c, const unsigned* a,
                                         unsigned b0, unsigned b1) {
    asm volatile(
        "mma.sync.aligned.m16n8k16.row.col.f32.f16.f16.f32 "
        "{%0,%1,%2,%3}, {%4,%5,%6,%7}, {%8,%9}, {%0,%1,%2,%3};"
        : "+f"(c[0]), "+f"(c[1]), "+f"(c[2]), "+f"(c[3])
        : "r"(a[0]), "r"(a[1]), "r"(a[2]), "r"(a[3]), "r"(b0), "r"(b1));
}

#define LDA 136   // padded smem stride in halves

template <typename TIn>
__global__ __launch_bounds__(256)
void k_gemm_tc(const TIn* __restrict__ A, const float* __restrict__ rs,
               const __half* __restrict__ Whi, const __half* __restrict__ Wlo,
               __half* __restrict__ Cm, int nrows, int ntiles) {
    extern __shared__ __half sm[];
    __half* As = sm;                    // 128 x LDA
    __half* Bh = sm + 128 * LDA;        // 128 x LDA  (Wt hi, [n][k])
    __half* Bl = Bh + 128 * LDA;        // 128 x LDA  (Wt lo)

    const int tid = threadIdx.x;
    const int wid = tid >> 5, lane = tid & 31;
    const int wr = wid >> 1;
    const int wc = wid & 1;
    const int g = lane >> 2, tg = lane & 3;

    for (int j = tid; j < 2048; j += 256) {
        int n = j >> 4, kc = (j & 15) * 8;
        *(uint4*)(Bh + n * LDA + kc) = *(const uint4*)(Whi + n * D + kc);
        *(uint4*)(Bl + n * LDA + kc) = *(const uint4*)(Wlo + n * D + kc);
    }

    for (int tile = blockIdx.x; tile < ntiles; tile += gridDim.x) {
        const int rowBase = tile * 128;
        __syncthreads();
        if constexpr (sizeof(TIn) == 2) {
            for (int j = tid; j < 2048; j += 256) {
                int r = j >> 4, kc = (j & 15) * 8;
                int gr = rowBase + r;
                uint4 v = make_uint4(0u, 0u, 0u, 0u);
                if (gr < nrows) v = *(const uint4*)((const __half*)A + (size_t)gr * D + kc);
                *(uint4*)(As + r * LDA + kc) = v;
            }
        } else {
            for (int j = tid; j < 4096; j += 256) {
                int r = j >> 5, kc = (j & 31) * 4;
                int gr = rowBase + r;
                __half2 o[2];
                if (gr < nrows) {
                    float s = rs[gr];
                    float4 v = *(const float4*)((const float*)A + (size_t)gr * D + kc);
                    o[0] = __floats2half2_rn(v.x * s, v.y * s);
                    o[1] = __floats2half2_rn(v.z * s, v.w * s);
                } else {
                    o[0] = __half2half2(__float2half(0.f));
                    o[1] = o[0];
                }
                *(uint2*)(As + r * LDA + kc) = *(uint2*)o;
            }
        }
        __syncthreads();

        float acc[2][8][4];
#pragma unroll
        for (int mt = 0; mt < 2; mt++)
#pragma unroll
            for (int nt = 0; nt < 8; nt++)
#pragma unroll
                for (int q = 0; q < 4; q++) acc[mt][nt][q] = 0.0f;

#pragma unroll
        for (int ks = 0; ks < 8; ks++) {
            const int k0 = ks * 16;
            unsigned a[2][4];
#pragma unroll
            for (int mt = 0; mt < 2; mt++) {
                const __half* pr = As + (wr * 32 + mt * 16 + g) * LDA + k0 + tg * 2;
                a[mt][0] = *(const unsigned*)(pr);
                a[mt][1] = *(const unsigned*)(pr + 8 * LDA);
                a[mt][2] = *(const unsigned*)(pr + 8);
                a[mt][3] = *(const unsigned*)(pr + 8 * LDA + 8);
            }
#pragma unroll
            for (int nt = 0; nt < 8; nt++) {
                const int n = wc * 64 + nt * 8 + g;
                const __half* ph = Bh + n * LDA + k0 + tg * 2;
                const __half* pl = Bl + n * LDA + k0 + tg * 2;
                unsigned bh0 = *(const unsigned*)(ph);
                unsigned bh1 = *(const unsigned*)(ph + 8);
                unsigned bl0 = *(const unsigned*)(pl);
                unsigned bl1 = *(const unsigned*)(pl + 8);
#pragma unroll
                for (int mt = 0; mt < 2; mt++) {
                    mma16816(acc[mt][nt], a[mt], bh0, bh1);
                    mma16816(acc[mt][nt], a[mt], bl0, bl1);
                }
            }
        }

#pragma unroll
        for (int mt = 0; mt < 2; mt++) {
            int r0 = rowBase + wr * 32 + mt * 16 + g;
            int r1 = r0 + 8;
#pragma unroll
            for (int nt = 0; nt < 8; nt++) {
                int col = wc * 64 + nt * 8 + tg * 2;
                if (r0 < nrows)
                    *(__half2*)(Cm + (size_t)r0 * D + col) =
                        __floats2half2_rn(acc[mt][nt][0], acc[mt][nt][1]);
                if (r1 < nrows)
                    *(__half2*)(Cm + (size_t)r1 * D + col) =
                        __floats2half2_rn(acc[mt][nt][2], acc[mt][nt][3]);
            }
        }
    }
}

// ---------------- gather + fused epilogue (fp16 in / fp16 out) ----------------
__global__ __launch_bounds__(256)
void k_gather(const int* __restrict__ csr, const int* __restrict__ rowp,
              const __half* __restrict__ A, const float* __restrict__ isq,
              const float* __restrict__ b, const float* __restrict__ oq,
              int scale_oq, __half* __restrict__ out, int n) {
    int w = (blockIdx.x * blockDim.x + threadIdx.x) >> 5;
    if (w >= n) return;
    int lane = threadIdx.x & 31;
    int s0 = rowp[w], s1 = rowp[w + 1];
    float4 acc = make_float4(0.f, 0.f, 0.f, 0.f);
    const unsigned FULL = 0xffffffffu;
    int col = lane * 4;

    for (int base = s0; base < s1; base += 32) {
        int cnt = min(32, s1 - base);
        int myidx = (lane < cnt) ? csr[base + lane] : 0;
        int t = 0;
        for (; t + 8 <= cnt; t += 8) {
            uint2 r[8];
#pragma unroll
            for (int u = 0; u < 8; u++) {
                int s = __shfl_sync(FULL, myidx, t + u);
                r[u] = *(const uint2*)(A + (size_t)s * D + col);
            }
#pragma unroll
            for (int u = 0; u < 8; u++) {
                float2 a = __half22float2(*(__half2*)&r[u].x);
                float2 bb = __half22float2(*(__half2*)&r[u].y);
                acc.x += a.x; acc.y += a.y; acc.z += bb.x; acc.w += bb.y;
            }
        }
        for (; t < cnt; t++) {
            int s = __shfl_sync(FULL, myidx, t);
            uint2 r = *(const uint2*)(A + (size_t)s * D + col);
            float2 a = __half22float2(*(__half2*)&r.x);
            float2 bb = __half22float2(*(__half2*)&r.y);
            acc.x += a.x; acc.y += a.y; acc.z += bb.x; acc.w += bb.y;
        }
    }

    float sc = isq[w];
    float post = scale_oq ? oq[w] : 1.0f;
    float4 bb = *(const float4*)(b + col);
    float2 r0, r1;
    r0.x = fmaxf(fmaf(acc.x, sc, bb.x), 0.0f) * post;
    r0.y = fmaxf(fmaf(acc.y, sc, bb.y), 0.0f) * post;
    r1.x = fmaxf(fmaf(acc.z, sc, bb.z), 0.0f) * post;
    r1.y = fmaxf(fmaf(acc.w, sc, bb.w), 0.0f) * post;
    __half2 o[2] = {__float22half2_rn(r0), __float22half2_rn(r1)};
    *(uint2*)(out + (size_t)w * D + col) = *(uint2*)o;
}

// ---------------- pooling: per-graph feature sums (fp16 input) -----------------
__global__ __launch_bounds__(128)
void k_pool(const __half* __restrict__ h, const int* __restrict__ n2g, int n) {
    int tid = threadIdx.x;
    int base = blockIdx.x * 64;
    int end = min(base + 64, n);
    if (base >= n) return;
    int curg = n2g[base];
    float acc = 0.0f;
    for (int node = base; node < end; node++) {
        int g = n2g[node];
        if (g != curg) {
            atomicAdd(&g_sums[curg * D + tid], acc);
            curg = g;
            acc = 0.0f;
        }
        acc += __half2float(h[(size_t)node * D + tid]);
    }
    atomicAdd(&g_sums[curg * D + tid], acc);
}

// ---------------- final: mean -> linear -> softmax -----------------------------
__global__ __launch_bounds__(128)
void k_final(const float* __restrict__ Wl, const float* __restrict__ bl,
             float* __restrict__ out) {
    __shared__ float hg[G * D];
    __shared__ float logits[G * C];
    int tid = threadIdx.x;
#pragma unroll
    for (int g = 0; g < G; g++)
        hg[g * D + tid] = g_sums[g * D + tid] / fmaxf(g_counts[g], 1.0f);
    __syncthreads();
    if (tid < G * C) {
        int g = tid / C, c = tid % C;
        float acc = bl[c];
        for (int k = 0; k < D; k++) acc = fmaf(hg[g * D + k], Wl[k * C + c], acc);
        logits[tid] = acc;
    }
    __syncthreads();
    if (tid < G) {
        float m = -1e30f;
        for (int c = 0; c < C; c++) m = fmaxf(m, logits[tid * C + c]);
        float s = 0.0f;
        float e[C];
        for (int c = 0; c < C; c++) { e[c] = expf(logits[tid * C + c] - m); s += e[c]; }
        float inv = 1.0f / s;
        for (int c = 0; c < C; c++) out[tid * C + c] = e[c] * inv;
    }
}

// ---------------- launch --------------------------------------------------------
extern "C" void kernel_launch(void* const* d_in, const int* in_sizes, int n_in,
                              void* d_out, int out_size) {
    const float* x   = (const float*)d_in[0];
    const int*   ei  = (const int*)d_in[1];
    const int*   n2g = (const int*)d_in[2];
    const float* W1  = (const float*)d_in[3];
    const float* b1  = (const float*)d_in[4];
    const float* W2  = (const float*)d_in[5];
    const float* b2  = (const float*)d_in[6];
    const float* Wl  = (const float*)d_in[7];
    const float* bl  = (const float*)d_in[8];
    float* out = (float*)d_out;

    const int N = in_sizes[2];          // 50000
    const int E = in_sizes[1] / 2;      // 800000

    float* outq = nullptr; cudaGetSymbolAddress((void**)&outq, g_out_isqrt);
    float* inq  = nullptr; cudaGetSymbolAddress((void**)&inq,  g_in_isqrt);
    __half* hA  = nullptr; cudaGetSymbolAddress((void**)&hA, g_h16A);
    __half* hB  = nullptr; cudaGetSymbolAddress((void**)&hB, g_h16B);
    __half* w1h = nullptr; cudaGetSymbolAddress((void**)&w1h, g_W1hi);
    __half* w1l = nullptr; cudaGetSymbolAddress((void**)&w1l, g_W1lo);
    __half* w2h = nullptr; cudaGetSymbolAddress((void**)&w2h, g_W2hi);
    __half* w2l = nullptr; cudaGetSymbolAddress((void**)&w2l, g_W2lo);
    float* sums = nullptr; cudaGetSymbolAddress((void**)&sums, g_sums);
    float* cnts = nullptr; cudaGetSymbolAddress((void**)&cnts, g_counts);
    int* outc = nullptr; cudaGetSymbolAddress((void**)&outc, g_outcnt);
    int* inc  = nullptr; cudaGetSymbolAddress((void**)&inc,  g_incnt);
    int* rowp = nullptr; cudaGetSymbolAddress((void**)&rowp, g_rowptr);
    int* cur  = nullptr; cudaGetSymbolAddress((void**)&cur,  g_cursor);
    int* csr  = nullptr; cudaGetSymbolAddress((void**)&csr,  g_csr);
    int* bsum = nullptr; cudaGetSymbolAddress((void**)&bsum, g_bsums);

    const int nb = (N + 255) / 256;
    const int ntiles = (N + 127) / 128;
    const int gemmBlocks = 296;
    const int gatherBlocks = (N * 32 + 255) / 256;
    const int smemGemm = 3 * 128 * LDA * (int)sizeof(__half);   // 104448

    static cudaStream_t s1;
    static cudaEvent_t ev_fork, ev_csr;
    static int s_init = 0;
    if (!s_init) {
        cudaFuncSetAttribute(k_gemm_tc<float>,
                             cudaFuncAttributeMaxDynamicSharedMemorySize, smemGemm);
        cudaFuncSetAttribute(k_gemm_tc<__half>,
                             cudaFuncAttributeMaxDynamicSharedMemorySize, smemGemm);
        cudaStreamCreateWithFlags(&s1, cudaStreamNonBlocking);
        cudaEventCreateWithFlags(&ev_fork, cudaEventDisableTiming);
        cudaEventCreateWithFlags(&ev_csr, cudaEventDisableTiming);
        s_init = 1;
    }

    // ---- stream 0: degrees + norms ----
    k_zero_i2<<<nb, 256>>>(outc, inc, N);                              // 0
    k_degcount<<<(E + 255) / 256, 256>>>(ei, E, outc, inc);            // 1
    k_out_isqrt<<<nb, 256>>>(outc, outq, N, sums, cnts);               // 2

    // fork: CSR build on s1
    cudaEventRecord(ev_fork, 0);
    cudaStreamWaitEvent(s1, ev_fork, 0);

    k_wconv<<<(D * D + 255) / 256, 256>>>(W1, W2, w1h, w1l, w2h, w2l); // 3
    k_scan1<<<nb, 256, 0, s1>>>(inc, N, bsum);                         // 4
    // 5 (profiled slot): layer-1 GEMM, fused fp32 conversion + oq scale
    k_gemm_tc<float><<<gemmBlocks, 256, smemGemm>>>(x, outq, w1h, w1l, hA, N, ntiles);
    k_scan2<<<1, 256, 0, s1>>>(bsum, nb, E, rowp, N);                  // 6
    k_scan3<<<nb, 256, 0, s1>>>(inc, N, bsum, rowp, cur, inq, n2g, cnts); // 7
    k_fill<<<(E + 255) / 256, 256, 0, s1>>>(ei, E, cur, csr);          // 8

    // join: gather1 needs CSR + gemm1
    cudaEventRecord(ev_csr, s1);
    cudaStreamWaitEvent(0, ev_csr, 0);

    k_gather<<<gatherBlocks, 256>>>(csr, rowp, hA, inq, b1, outq, 1, hB, N);
    k_gemm_tc<__half><<<gemmBlocks, 256, smemGemm>>>(hB, outq, w2h, w2l, hA, N, ntiles);
    k_gather<<<gatherBlocks, 256>>>(csr, rowp, hA, inq, b2, outq, 0, hB, N);

    k_pool<<<(N + 63) / 64, 128>>>(hB, n2g, N);
    k_final<<<1, 128>>>(Wl, bl, out);
}

// round 8
// speedup vs baseline: 3.1254x; 1.4224x over previous
#include <cuda_runtime.h>
#include <cuda_fp16.h>

#define NN 50000
#define EE 800000
#define D  128
#define G  8
#define C  10

// ---------------- scratch (static device globals; no allocs allowed) --------
__device__ float  g_out_isqrt[NN];
__device__ float  g_in_isqrt[NN];
__device__ __half g_h16A[NN * D];
__device__ __half g_h16B[NN * D];
__device__ __half g_W1hi[D * D];
__device__ __half g_W1lo[D * D];
__device__ __half g_W2hi[D * D];
__device__ __half g_W2lo[D * D];
__device__ float  g_sums[G * D];
__device__ int    g_outcnt[NN];
__device__ int    g_incnt[NN];
__device__ int    g_rowptr[NN + 1];
__device__ int    g_cursor[NN];
__device__ int    g_csr[EE];
__device__ int    g_bsums[256];

// ---------------- setup: zero degree arrays + pool sums, convert weights ------
__global__ __launch_bounds__(256)
void k_setup(int* __restrict__ outc, int* __restrict__ inc, int n,
             float* __restrict__ sums,
             const float* __restrict__ W1, const float* __restrict__ W2,
             __half* __restrict__ w1h, __half* __restrict__ w1l,
             __half* __restrict__ w2h, __half* __restrict__ w2l) {
    int i = blockIdx.x * 256 + threadIdx.x;
    if (i < n) { outc[i] = 0; inc[i] = 0; }
    if (i < G * D) sums[i] = 0.0f;
    if (i < D * D) {
        int k = i >> 7, nn = i & 127;
        float v = W1[i];
        __half hi = __float2half_rn(v);
        w1h[nn * D + k] = hi;
        w1l[nn * D + k] = __float2half_rn(v - __half2float(hi));
        v = W2[i];
        hi = __float2half_rn(v);
        w2h[nn * D + k] = hi;
        w2l[nn * D + k] = __float2half_rn(v - __half2float(hi));
    }
}

// ---------------- degree histograms (int) ------------------------------------
__global__ void k_degcount(const int* __restrict__ ei, int E,
                           int* __restrict__ outc, int* __restrict__ inc) {
    int e = blockIdx.x * blockDim.x + threadIdx.x;
    if (e < E) {
        atomicAdd(&outc[ei[e]], 1);
        atomicAdd(&inc[ei[E + e]], 1);
    }
}

// ---------------- scan helpers -------------------------------------------------
__device__ __forceinline__ int warp_incl_scan(int v, int lane) {
#pragma unroll
    for (int o = 1; o < 32; o <<= 1) {
        int t = __shfl_up_sync(0xffffffffu, v, o);
        if (lane >= o) v += t;
    }
    return v;
}

__device__ __forceinline__ int block_incl_scan(int v, int tid, int* ws) {
    int lane = tid & 31, wid = tid >> 5;
    int s = warp_incl_scan(v, lane);
    if (lane == 31) ws[wid] = s;
    __syncthreads();
    if (wid == 0) {
        int t = (lane < 8) ? ws[lane] : 0;
        t = warp_incl_scan(t, lane);
        if (lane < 8) ws[lane] = t;
    }
    __syncthreads();
    return s + (wid > 0 ? ws[wid - 1] : 0);
}

// pass 1: per-block (256-wide) sums of in-degrees; also out_isqrt
__global__ __launch_bounds__(256)
void k_scan1(const int* __restrict__ inc, const int* __restrict__ outc, int n,
             int* __restrict__ bsums, float* __restrict__ oq) {
    __shared__ int ws[8];
    int tid = threadIdx.x;
    int i = blockIdx.x * 256 + tid;
    int v = (i < n) ? inc[i] : 0;
    int incl = block_incl_scan(v, tid, ws);
    if (tid == 255) bsums[blockIdx.x] = incl;
    if (i < n) oq[i] = rsqrtf((float)max(outc[i], 1));
}

// pass 2 (fused): each block re-scans the block sums locally, then its tile
__global__ __launch_bounds__(256)
void k_scan3(const int* __restrict__ inc, int n, int nb, int E,
             const int* __restrict__ bsums, int* __restrict__ rowp,
             int* __restrict__ cur, float* __restrict__ iq) {
    __shared__ int ws[8];
    __shared__ int soff[256];
    int tid = threadIdx.x;

    int vb = (tid < nb) ? bsums[tid] : 0;
    int inclb = block_incl_scan(vb, tid, ws);
    soff[tid] = inclb - vb;
    __syncthreads();
    int blockoff = soff[blockIdx.x];
    __syncthreads();

    int i = blockIdx.x * 256 + tid;
    int v = (i < n) ? inc[i] : 0;
    int incl = block_incl_scan(v, tid, ws);
    if (i < n) {
        int ex = incl - v + blockoff;
        rowp[i] = ex;
        cur[i] = ex;
        iq[i] = rsqrtf((float)max(v, 1));
    }
    if (blockIdx.x == 0 && tid == 0) rowp[n] = E;
}

// ---------------- CSR fill: bucket src indices by dst -------------------------
__global__ void k_fill(const int* __restrict__ ei, int E,
                       int* __restrict__ cur, int* __restrict__ csr) {
    int e = blockIdx.x * blockDim.x + threadIdx.x;
    if (e < E) {
        int d = ei[E + e];
        int pos = atomicAdd(&cur[d], 1);
        csr[pos] = ei[e];
    }
}

// ---------------- tensor-core GEMM: Cm = A @ (Whi + Wlo), fp16 out ------------
__device__ __forceinline__ void mma16816(float* c, const unsigned* a,
                                         unsigned b0, unsigned b1) {
    asm volatile(
        "mma.sync.aligned.m16n8k16.row.col.f32.f16.f16.f32 "
        "{%0,%1,%2,%3}, {%4,%5,%6,%7}, {%8,%9}, {%0,%1,%2,%3};"
        : "+f"(c[0]), "+f"(c[1]), "+f"(c[2]), "+f"(c[3])
        : "r"(a[0]), "r"(a[1]), "r"(a[2]), "r"(a[3]), "r"(b0), "r"(b1));
}

#define LDA 136   // padded smem stride in halves

template <typename TIn>
__global__ __launch_bounds__(256)
void k_gemm_tc(const TIn* __restrict__ A, const float* __restrict__ rs,
               const __half* __restrict__ Whi, const __half* __restrict__ Wlo,
               __half* __restrict__ Cm, int nrows, int ntiles) {
    extern __shared__ __half sm[];
    __half* As = sm;
    __half* Bh = sm + 128 * LDA;
    __half* Bl = Bh + 128 * LDA;

    const int tid = threadIdx.x;
    const int wid = tid >> 5, lane = tid & 31;
    const int wr = wid >> 1;
    const int wc = wid & 1;
    const int g = lane >> 2, tg = lane & 3;

    for (int j = tid; j < 2048; j += 256) {
        int n = j >> 4, kc = (j & 15) * 8;
        *(uint4*)(Bh + n * LDA + kc) = *(const uint4*)(Whi + n * D + kc);
        *(uint4*)(Bl + n * LDA + kc) = *(const uint4*)(Wlo + n * D + kc);
    }

    for (int tile = blockIdx.x; tile < ntiles; tile += gridDim.x) {
        const int rowBase = tile * 128;
        __syncthreads();
        if constexpr (sizeof(TIn) == 2) {
            for (int j = tid; j < 2048; j += 256) {
                int r = j >> 4, kc = (j & 15) * 8;
                int gr = rowBase + r;
                uint4 v = make_uint4(0u, 0u, 0u, 0u);
                if (gr < nrows) v = *(const uint4*)((const __half*)A + (size_t)gr * D + kc);
                *(uint4*)(As + r * LDA + kc) = v;
            }
        } else {
            for (int j = tid; j < 4096; j += 256) {
                int r = j >> 5, kc = (j & 31) * 4;
                int gr = rowBase + r;
                __half2 o[2];
                if (gr < nrows) {
                    float s = rs[gr];
                    float4 v = *(const float4*)((const float*)A + (size_t)gr * D + kc);
                    o[0] = __floats2half2_rn(v.x * s, v.y * s);
                    o[1] = __floats2half2_rn(v.z * s, v.w * s);
                } else {
                    o[0] = __half2half2(__float2half(0.f));
                    o[1] = o[0];
                }
                *(uint2*)(As + r * LDA + kc) = *(uint2*)o;
            }
        }
        __syncthreads();

        float acc[2][8][4];
#pragma unroll
        for (int mt = 0; mt < 2; mt++)
#pragma unroll
            for (int nt = 0; nt < 8; nt++)
#pragma unroll
                for (int q = 0; q < 4; q++) acc[mt][nt][q] = 0.0f;

#pragma unroll
        for (int ks = 0; ks < 8; ks++) {
            const int k0 = ks * 16;
            unsigned a[2][4];
#pragma unroll
            for (int mt = 0; mt < 2; mt++) {
                const __half* pr = As + (wr * 32 + mt * 16 + g) * LDA + k0 + tg * 2;
                a[mt][0] = *(const unsigned*)(pr);
                a[mt][1] = *(const unsigned*)(pr + 8 * LDA);
                a[mt][2] = *(const unsigned*)(pr + 8);
                a[mt][3] = *(const unsigned*)(pr + 8 * LDA + 8);
            }
#pragma unroll
            for (int nt = 0; nt < 8; nt++) {
                const int n = wc * 64 + nt * 8 + g;
                const __half* ph = Bh + n * LDA + k0 + tg * 2;
                const __half* pl = Bl + n * LDA + k0 + tg * 2;
                unsigned bh0 = *(const unsigned*)(ph);
                unsigned bh1 = *(const unsigned*)(ph + 8);
                unsigned bl0 = *(const unsigned*)(pl);
                unsigned bl1 = *(const unsigned*)(pl + 8);
#pragma unroll
                for (int mt = 0; mt < 2; mt++) {
                    mma16816(acc[mt][nt], a[mt], bh0, bh1);
                    mma16816(acc[mt][nt], a[mt], bl0, bl1);
                }
            }
        }

#pragma unroll
        for (int mt = 0; mt < 2; mt++) {
            int r0 = rowBase + wr * 32 + mt * 16 + g;
            int r1 = r0 + 8;
#pragma unroll
            for (int nt = 0; nt < 8; nt++) {
                int col = wc * 64 + nt * 8 + tg * 2;
                if (r0 < nrows)
                    *(__half2*)(Cm + (size_t)r0 * D + col) =
                        __floats2half2_rn(acc[mt][nt][0], acc[mt][nt][1]);
                if (r1 < nrows)
                    *(__half2*)(Cm + (size_t)r1 * D + col) =
                        __floats2half2_rn(acc[mt][nt][2], acc[mt][nt][3]);
            }
        }
    }
}

// ---------------- gather + fused epilogue (+ optional fused pooling) ----------
// DO_POOL: also accumulate relu output into g_sums via smem buckets.
template <int DO_POOL>
__global__ __launch_bounds__(256)
void k_gather(const int* __restrict__ csr, const int* __restrict__ rowp,
              const __half* __restrict__ A, const float* __restrict__ isq,
              const float* __restrict__ b, const float* __restrict__ oq,
              int scale_oq, __half* __restrict__ out, int n,
              const int* __restrict__ n2g) {
    __shared__ float sacc[DO_POOL ? G * D : 1];
    if (DO_POOL) {
        for (int j = threadIdx.x; j < G * D; j += 256) sacc[j] = 0.0f;
        __syncthreads();
    }

    int w = (blockIdx.x * blockDim.x + threadIdx.x) >> 5;
    int lane = threadIdx.x & 31;
    int col = lane * 4;

    if (w < n) {
        int s0 = rowp[w], s1 = rowp[w + 1];
        float4 acc = make_float4(0.f, 0.f, 0.f, 0.f);
        const unsigned FULL = 0xffffffffu;

        for (int base = s0; base < s1; base += 32) {
            int cnt = min(32, s1 - base);
            int myidx = (lane < cnt) ? csr[base + lane] : 0;
            int t = 0;
            for (; t + 8 <= cnt; t += 8) {
                uint2 r[8];
#pragma unroll
                for (int u = 0; u < 8; u++) {
                    int s = __shfl_sync(FULL, myidx, t + u);
                    r[u] = *(const uint2*)(A + (size_t)s * D + col);
                }
#pragma unroll
                for (int u = 0; u < 8; u++) {
                    float2 a = __half22float2(*(__half2*)&r[u].x);
                    float2 bb = __half22float2(*(__half2*)&r[u].y);
                    acc.x += a.x; acc.y += a.y; acc.z += bb.x; acc.w += bb.y;
                }
            }
            for (; t < cnt; t++) {
                int s = __shfl_sync(FULL, myidx, t);
                uint2 r = *(const uint2*)(A + (size_t)s * D + col);
                float2 a = __half22float2(*(__half2*)&r.x);
                float2 bb = __half22float2(*(__half2*)&r.y);
                acc.x += a.x; acc.y += a.y; acc.z += bb.x; acc.w += bb.y;
            }
        }

        float sc = isq[w];
        float post = scale_oq ? oq[w] : 1.0f;
        float4 bb = *(const float4*)(b + col);
        float2 r0, r1;
        r0.x = fmaxf(fmaf(acc.x, sc, bb.x), 0.0f) * post;
        r0.y = fmaxf(fmaf(acc.y, sc, bb.y), 0.0f) * post;
        r1.x = fmaxf(fmaf(acc.z, sc, bb.z), 0.0f) * post;
        r1.y = fmaxf(fmaf(acc.w, sc, bb.w), 0.0f) * post;
        __half2 o[2] = {__float22half2_rn(r0), __float22half2_rn(r1)};
        *(uint2*)(out + (size_t)w * D + col) = *(uint2*)o;

        if (DO_POOL) {
            int gidx = n2g[w] * D + col;
            atomicAdd(&sacc[gidx + 0], r0.x);
            atomicAdd(&sacc[gidx + 1], r0.y);
            atomicAdd(&sacc[gidx + 2], r1.x);
            atomicAdd(&sacc[gidx + 3], r1.y);
        }
    }

    if (DO_POOL) {
        __syncthreads();
        for (int j = threadIdx.x; j < G * D; j += 256) {
            float v = sacc[j];
            if (v != 0.0f) atomicAdd(&g_sums[j], v);
        }
    }
}

// ---------------- final: counts via binary search, mean -> linear -> softmax --
__global__ __launch_bounds__(128)
void k_final(const float* __restrict__ Wl, const float* __restrict__ bl,
             const int* __restrict__ n2g, int n, float* __restrict__ out) {
    __shared__ float hg[G * D];
    __shared__ float logits[G * C];
    __shared__ float scnt[G];
    int tid = threadIdx.x;
    if (tid < G) {
        // lower_bound for graph tid and tid+1
        int lo = 0, hi = n;
        while (lo < hi) { int m = (lo + hi) >> 1; if (n2g[m] < tid) lo = m + 1; else hi = m; }
        int lo2 = lo, hi2 = n;
        while (lo2 < hi2) { int m = (lo2 + hi2) >> 1; if (n2g[m] < tid + 1) lo2 = m + 1; else hi2 = m; }
        scnt[tid] = fmaxf((float)(lo2 - lo), 1.0f);
    }
    __syncthreads();
#pragma unroll
    for (int g = 0; g < G; g++)
        hg[g * D + tid] = g_sums[g * D + tid] / scnt[g];
    __syncthreads();
    if (tid < G * C) {
        int g = tid / C, c = tid % C;
        float acc = bl[c];
        for (int k = 0; k < D; k++) acc = fmaf(hg[g * D + k], Wl[k * C + c], acc);
        logits[tid] = acc;
    }
    __syncthreads();
    if (tid < G) {
        float m = -1e30f;
        for (int c = 0; c < C; c++) m = fmaxf(m, logits[tid * C + c]);
        float s = 0.0f;
        float e[C];
        for (int c = 0; c < C; c++) { e[c] = expf(logits[tid * C + c] - m); s += e[c]; }
        float inv = 1.0f / s;
        for (int c = 0; c < C; c++) out[tid * C + c] = e[c] * inv;
    }
}

// ---------------- launch --------------------------------------------------------
extern "C" void kernel_launch(void* const* d_in, const int* in_sizes, int n_in,
                              void* d_out, int out_size) {
    const float* x   = (const float*)d_in[0];
    const int*   ei  = (const int*)d_in[1];
    const int*   n2g = (const int*)d_in[2];
    const float* W1  = (const float*)d_in[3];
    const float* b1  = (const float*)d_in[4];
    const float* W2  = (const float*)d_in[5];
    const float* b2  = (const float*)d_in[6];
    const float* Wl  = (const float*)d_in[7];
    const float* bl  = (const float*)d_in[8];
    float* out = (float*)d_out;

    const int N = in_sizes[2];
    const int E = in_sizes[1] / 2;

    float* outq = nullptr; cudaGetSymbolAddress((void**)&outq, g_out_isqrt);
    float* inq  = nullptr; cudaGetSymbolAddress((void**)&inq,  g_in_isqrt);
    __half* hA  = nullptr; cudaGetSymbolAddress((void**)&hA, g_h16A);
    __half* hB  = nullptr; cudaGetSymbolAddress((void**)&hB, g_h16B);
    __half* w1h = nullptr; cudaGetSymbolAddress((void**)&w1h, g_W1hi);
    __half* w1l = nullptr; cudaGetSymbolAddress((void**)&w1l, g_W1lo);
    __half* w2h = nullptr; cudaGetSymbolAddress((void**)&w2h, g_W2hi);
    __half* w2l = nullptr; cudaGetSymbolAddress((void**)&w2l, g_W2lo);
    float* sums = nullptr; cudaGetSymbolAddress((void**)&sums, g_sums);
    int* outc = nullptr; cudaGetSymbolAddress((void**)&outc, g_outcnt);
    int* inc  = nullptr; cudaGetSymbolAddress((void**)&inc,  g_incnt);
    int* rowp = nullptr; cudaGetSymbolAddress((void**)&rowp, g_rowptr);
    int* cur  = nullptr; cudaGetSymbolAddress((void**)&cur,  g_cursor);
    int* csr  = nullptr; cudaGetSymbolAddress((void**)&csr,  g_csr);
    int* bsum = nullptr; cudaGetSymbolAddress((void**)&bsum, g_bsums);

    const int nb = (N + 255) / 256;
    const int ntiles = (N + 127) / 128;
    const int gemmBlocks = 296;
    const int gatherBlocks = (N * 32 + 255) / 256;
    const int smemGemm = 3 * 128 * LDA * (int)sizeof(__half);

    static cudaStream_t s1;
    static cudaEvent_t ev_fork, ev_csr;
    static int s_init = 0;
    if (!s_init) {
        cudaFuncSetAttribute(k_gemm_tc<float>,
                             cudaFuncAttributeMaxDynamicSharedMemorySize, smemGemm);
        cudaFuncSetAttribute(k_gemm_tc<__half>,
                             cudaFuncAttributeMaxDynamicSharedMemorySize, smemGemm);
        cudaStreamCreateWithFlags(&s1, cudaStreamNonBlocking);
        cudaEventCreateWithFlags(&ev_fork, cudaEventDisableTiming);
        cudaEventCreateWithFlags(&ev_csr, cudaEventDisableTiming);
        s_init = 1;
    }

    // 0: setup (zeros + weight conversion)
    k_setup<<<nb, 256>>>(outc, inc, N, sums, W1, W2, w1h, w1l, w2h, w2l);
    // 1: degrees
    k_degcount<<<(E + 255) / 256, 256>>>(ei, E, outc, inc);
    // 2: block sums of in-degree + out_isqrt
    k_scan1<<<nb, 256>>>(inc, outc, N, bsum, outq);

    // fork: CSR finish on s1, layer-1 GEMM on main
    cudaEventRecord(ev_fork, 0);
    cudaStreamWaitEvent(s1, ev_fork, 0);

    k_scan3<<<nb, 256, 0, s1>>>(inc, N, nb, E, bsum, rowp, cur, inq);
    k_fill<<<(E + 255) / 256, 256, 0, s1>>>(ei, E, cur, csr);
    k_gemm_tc<float><<<gemmBlocks, 256, smemGemm>>>(x, outq, w1h, w1l, hA, N, ntiles);

    cudaEventRecord(ev_csr, s1);
    cudaStreamWaitEvent(0, ev_csr, 0);

    // layer 1 gather (folds oq for next gemm), layer 2, gather2 + fused pool
    k_gather<0><<<gatherBlocks, 256>>>(csr, rowp, hA, inq, b1, outq, 1, hB, N, n2g);
    k_gemm_tc<__half><<<gemmBlocks, 256, smemGemm>>>(hB, outq, w2h, w2l, hA, N, ntiles);
    k_gather<1><<<gatherBlocks, 256>>>(csr, rowp, hA, inq, b2, outq, 0, hB, N, n2g);

    // head
    k_final<<<1, 128>>>(Wl, bl, n2g, N, out);
}